// round 7
// baseline (speedup 1.0000x reference)
#include <cuda_runtime.h>

#define E_EDGES 400000
#define TILE 128
#define NTHR 256

// ---------------- scratch (__device__ globals: allocation-free) ----------------
__device__ float g_t  [(size_t)E_EDGES * 64];    // silu(x_p4@w_down.T) [E,64]
__device__ float g_wt [194048];                  // folded+transposed weights (k-major)

// float offsets inside g_wt
#define WT_P2   0        // [128][128]
#define WT_P4   16384    // [128][128]
#define WT_SBFC 32768    // [44][128]  (folded w_sbf2@w_sbf1, rows 42..43 zero)
#define WT_DOWN 38400    // [128][64]
#define WT_TC   46592    // [296][64]  (folded w_t2@w_t1, rows 294..295 zero)
#define WT_UP   65536    // [64][128]
#define WT_RB1  73728    // [128][128]
#define WT_RB2  90112    // [128][128]
#define WT_LIN  106496   // [128][128]
#define WT_RA1  122880   // [2][128][128]
#define WT_RA2  155648   // [2][128][128]
#define WT_SBF  188416   // [44][128]  (w_sbf transposed, rows 42..43 zero)

typedef unsigned long long u64;

__device__ __forceinline__ float siluf(float x) {
    return __fdividef(x, 1.0f + __expf(-x));
}
__device__ __forceinline__ u64 pk2(float x, float y) {
    u64 r; asm("mov.b64 %0,{%1,%2};" : "=l"(r) : "f"(x), "f"(y)); return r;
}
__device__ __forceinline__ float2 upk2(u64 v) {
    float2 r; asm("mov.b64 {%0,%1},%2;" : "=f"(r.x), "=f"(r.y) : "l"(v)); return r;
}
__device__ __forceinline__ void ffma2(u64 &a, u64 x, u64 y) {
    asm("fma.rn.f32x2 %0,%1,%2,%0;" : "+l"(a) : "l"(x), "l"(y));
}

// ---------------- setup: fold rank-8 factors, transpose all weights to k-major ----------------
__global__ void setup_kernel(
    const float* __restrict__ w_p2, const float* __restrict__ w_p4,
    const float* __restrict__ w_sbf1, const float* __restrict__ w_sbf2,
    const float* __restrict__ w_t1, const float* __restrict__ w_t2,
    const float* __restrict__ w_down, const float* __restrict__ w_up,
    const float* __restrict__ rb_w1, const float* __restrict__ rb_w2,
    const float* __restrict__ w_lin,
    const float* __restrict__ ra_w1, const float* __restrict__ ra_w2,
    const float* __restrict__ w_sbf)
{
    int tid = blockIdx.x * blockDim.x + threadIdx.x;
    int nt = gridDim.x * blockDim.x;
    for (int i = tid; i < 16384; i += nt) {
        int k = i >> 7, j = i & 127;
        g_wt[WT_P2 + i]  = w_p2[j * 128 + k];
        g_wt[WT_P4 + i]  = w_p4[j * 128 + k];
        g_wt[WT_RB1 + i] = rb_w1[j * 128 + k];
        g_wt[WT_RB2 + i] = rb_w2[j * 128 + k];
        g_wt[WT_LIN + i] = w_lin[j * 128 + k];
        g_wt[WT_RA1 + i]          = ra_w1[j * 128 + k];
        g_wt[WT_RA1 + 16384 + i]  = ra_w1[16384 + j * 128 + k];
        g_wt[WT_RA2 + i]          = ra_w2[j * 128 + k];
        g_wt[WT_RA2 + 16384 + i]  = ra_w2[16384 + j * 128 + k];
    }
    for (int i = tid; i < 8192; i += nt) {   // w_down [64,128] -> [128][64]
        int k = i >> 6, j = i & 63;
        g_wt[WT_DOWN + i] = w_down[j * 128 + k];
    }
    for (int i = tid; i < 8192; i += nt) {   // w_up [128,64] -> [64][128]
        int k = i >> 7, j = i & 127;
        g_wt[WT_UP + i] = w_up[j * 64 + k];
    }
    for (int i = tid; i < 44 * 128; i += nt) { // folded sbf: C[j][k]=sum_b w_sbf2[j][b]*w_sbf1[b][k] -> [k][j]
        int k = i >> 7, j = i & 127; float v = 0.f;
        if (k < 42) {
            #pragma unroll
            for (int b = 0; b < 8; b++) v += w_sbf2[j * 8 + b] * w_sbf1[b * 42 + k];
        }
        g_wt[WT_SBFC + i] = v;
    }
    for (int i = tid; i < 44 * 128; i += nt) { // w_sbf [128,42] -> [44][128]
        int k = i >> 7, j = i & 127;
        g_wt[WT_SBF + i] = (k < 42) ? w_sbf[j * 42 + k] : 0.f;
    }
    for (int i = tid; i < 296 * 64; i += nt) { // folded t: T[j][k]=sum_b w_t2[j][b]*w_t1[b][k] -> [k][j]
        int k = i >> 6, j = i & 63; float v = 0.f;
        if (k < 294) {
            #pragma unroll
            for (int b = 0; b < 8; b++) v += w_t2[j * 8 + b] * w_t1[b * 294 + k];
        }
        g_wt[WT_TC + i] = v;
    }
}

// ---------------- GEMM micro-kernels (f32x2 packed FFMA) ----------------
// As: smem [128 rows][stride 128], row-major.  Ws: smem [K][N] k-major.
// Thread (tx in 0..15, ty in 0..15): rows ty*8..+7.
// N=128: cols tx*8..+7 (acc[8][4] f32x2 pairs). N=64: cols tx*4..+3 (acc[8][2]).

__device__ __forceinline__ void gemm_n128(const float* __restrict__ As,
                                          const float* __restrict__ Ws,
                                          int K, u64 acc[8][4], int tx, int ty)
{
    const float* arow = As + ty * 8 * 128;
    const float* wc = Ws + tx * 8;
    for (int k = 0; k < K; k += 4) {
        u64 bp[4][4];
        #pragma unroll
        for (int kk = 0; kk < 4; kk++) {
            float4 b0 = *(const float4*)(wc + (k + kk) * 128);
            float4 b1 = *(const float4*)(wc + (k + kk) * 128 + 4);
            bp[kk][0] = pk2(b0.x, b0.y); bp[kk][1] = pk2(b0.z, b0.w);
            bp[kk][2] = pk2(b1.x, b1.y); bp[kk][3] = pk2(b1.z, b1.w);
        }
        #pragma unroll
        for (int u = 0; u < 8; u++) {
            float4 a4 = *(const float4*)(arow + u * 128 + k);
            u64 ad0 = pk2(a4.x, a4.x), ad1 = pk2(a4.y, a4.y);
            u64 ad2 = pk2(a4.z, a4.z), ad3 = pk2(a4.w, a4.w);
            #pragma unroll
            for (int p = 0; p < 4; p++) ffma2(acc[u][p], ad0, bp[0][p]);
            #pragma unroll
            for (int p = 0; p < 4; p++) ffma2(acc[u][p], ad1, bp[1][p]);
            #pragma unroll
            for (int p = 0; p < 4; p++) ffma2(acc[u][p], ad2, bp[2][p]);
            #pragma unroll
            for (int p = 0; p < 4; p++) ffma2(acc[u][p], ad3, bp[3][p]);
        }
    }
}

__device__ __forceinline__ void gemm_n64(const float* __restrict__ As,
                                         const float* __restrict__ Ws,
                                         int K, u64 acc[8][2], int tx, int ty)
{
    const float* arow = As + ty * 8 * 128;
    const float* wc = Ws + tx * 4;
    for (int k = 0; k < K; k += 4) {
        u64 bp[4][2];
        #pragma unroll
        for (int kk = 0; kk < 4; kk++) {
            float4 b = *(const float4*)(wc + (k + kk) * 64);
            bp[kk][0] = pk2(b.x, b.y); bp[kk][1] = pk2(b.z, b.w);
        }
        #pragma unroll
        for (int u = 0; u < 8; u++) {
            float4 a4 = *(const float4*)(arow + u * 128 + k);
            u64 ad0 = pk2(a4.x, a4.x), ad1 = pk2(a4.y, a4.y);
            u64 ad2 = pk2(a4.z, a4.z), ad3 = pk2(a4.w, a4.w);
            ffma2(acc[u][0], ad0, bp[0][0]); ffma2(acc[u][1], ad0, bp[0][1]);
            ffma2(acc[u][0], ad1, bp[1][0]); ffma2(acc[u][1], ad1, bp[1][1]);
            ffma2(acc[u][0], ad2, bp[2][0]); ffma2(acc[u][1], ad2, bp[2][1]);
            ffma2(acc[u][0], ad3, bp[3][0]); ffma2(acc[u][1], ad3, bp[3][1]);
        }
    }
}

__device__ __forceinline__ void acc_bias128(u64 acc[8][4], const float* __restrict__ b, int tx) {
    float4 b0 = *(const float4*)(b + tx * 8);
    float4 b1 = *(const float4*)(b + tx * 8 + 4);
    u64 p0 = pk2(b0.x, b0.y), p1 = pk2(b0.z, b0.w);
    u64 p2 = pk2(b1.x, b1.y), p3 = pk2(b1.z, b1.w);
    #pragma unroll
    for (int u = 0; u < 8; u++) { acc[u][0] = p0; acc[u][1] = p1; acc[u][2] = p2; acc[u][3] = p3; }
}
__device__ __forceinline__ void acc_zero128(u64 acc[8][4]) {
    #pragma unroll
    for (int u = 0; u < 8; u++) { acc[u][0] = 0ull; acc[u][1] = 0ull; acc[u][2] = 0ull; acc[u][3] = 0ull; }
}
__device__ __forceinline__ void acc_zero64(u64 acc[8][2]) {
    #pragma unroll
    for (int u = 0; u < 8; u++) { acc[u][0] = 0ull; acc[u][1] = 0ull; }
}

// ---------------- staging helpers (all coalesced float4/float2) ----------------
__device__ __forceinline__ void stage_f4(float* dst, const float* __restrict__ src, int nf4) {
    const float4* s = (const float4*)src;
    float4* d = (float4*)dst;
    for (int i = threadIdx.x; i < nf4; i += NTHR) d[i] = s[i];
}
// sbf0 tile (row stride 42) -> smem [128][stride 128], cols 42..43 zeroed
__device__ __forceinline__ void stage_sbf(float* dst, const float* __restrict__ src) {
    for (int i = threadIdx.x; i < 128 * 22; i += NTHR) {
        int r = i / 22, c2 = i % 22;
        float2 v = (c2 < 21) ? *(const float2*)(src + (size_t)r * 42 + 2 * c2)
                             : make_float2(0.f, 0.f);
        *(float2*)(dst + r * 128 + 2 * c2) = v;
    }
}
// ta chunk (row stride 294) -> smem [128][stride 128], kc cols (kvalid real, rest zero)
__device__ __forceinline__ void stage_ta(float* dst, const float* __restrict__ src, int kc, int kvalid) {
    int c2n = kc >> 1;
    for (int i = threadIdx.x; i < 128 * c2n; i += NTHR) {
        int r = i / c2n, c2 = i % c2n;
        float2 v = (2 * c2 < kvalid) ? *(const float2*)(src + (size_t)r * 294 + 2 * c2)
                                     : make_float2(0.f, 0.f);
        *(float2*)(dst + r * 128 + 2 * c2) = v;
    }
}

// ---------------- Kernel A: t = silu((silu(x1@Wp4+b)*sbf)@Wdown) -> g_t ----------------
extern "C" __global__ void __launch_bounds__(NTHR, 1)
kernelA(const float* __restrict__ x1, const float* __restrict__ sbf0,
        const float* __restrict__ b_p4)
{
    extern __shared__ float sm[];
    float* A1 = sm;
    float* WB = sm + 16384;
    float* C  = sm + 32768;
    int tx = threadIdx.x & 15, ty = threadIdx.x >> 4;
    int r0 = blockIdx.x * TILE;

    stage_f4(A1, x1 + (size_t)r0 * 128, 4096);
    stage_f4(WB, g_wt + WT_P4, 4096);
    __syncthreads();

    u64 acc[8][4];
    // ---- silu(x1@Wp4 + b) -> C
    acc_bias128(acc, b_p4, tx);
    gemm_n128(A1, WB, 128, acc, tx, ty);
    #pragma unroll
    for (int u = 0; u < 8; u++) {
        int rs = (ty * 8 + u) * 128 + tx * 8;
        float2 v0 = upk2(acc[u][0]), v1 = upk2(acc[u][1]), v2 = upk2(acc[u][2]), v3 = upk2(acc[u][3]);
        *(float4*)(C + rs)     = make_float4(siluf(v0.x), siluf(v0.y), siluf(v1.x), siluf(v1.y));
        *(float4*)(C + rs + 4) = make_float4(siluf(v2.x), siluf(v2.y), siluf(v3.x), siluf(v3.y));
    }
    __syncthreads();   // all gemm reads of A1/WB done before restage

    // ---- sbf = sbf0 @ WsbfC  (K=44 padded)
    stage_sbf(A1, sbf0 + (size_t)r0 * 42);
    stage_f4(WB, g_wt + WT_SBFC, 1408);
    __syncthreads();
    acc_zero128(acc);
    gemm_n128(A1, WB, 44, acc, tx, ty);
    __syncthreads();   // all done reading A1/WB before overwrite
    #pragma unroll
    for (int u = 0; u < 8; u++) {
        int rs = (ty * 8 + u) * 128 + tx * 8;
        float4 c0 = *(const float4*)(C + rs);
        float4 c1 = *(const float4*)(C + rs + 4);
        float2 v0 = upk2(acc[u][0]), v1 = upk2(acc[u][1]), v2 = upk2(acc[u][2]), v3 = upk2(acc[u][3]);
        *(float4*)(A1 + rs)     = make_float4(v0.x * c0.x, v0.y * c0.y, v1.x * c0.z, v1.y * c0.w);
        *(float4*)(A1 + rs + 4) = make_float4(v2.x * c1.x, v2.y * c1.y, v3.x * c1.z, v3.y * c1.w);
    }
    stage_f4(WB, g_wt + WT_DOWN, 2048);
    __syncthreads();

    // ---- t = silu(x_p4 @ Wdown)  (N=64) -> g_t
    u64 acc2[8][2];
    acc_zero64(acc2);
    gemm_n64(A1, WB, 128, acc2, tx, ty);
    #pragma unroll
    for (int u = 0; u < 8; u++) {
        size_t rg = (size_t)(r0 + ty * 8 + u) * 64 + tx * 4;
        float2 v0 = upk2(acc2[u][0]), v1 = upk2(acc2[u][1]);
        *(float4*)(g_t + rg) = make_float4(siluf(v0.x), siluf(v0.y), siluf(v1.x), siluf(v1.y));
    }
}

// ---------------- residual block on smem P ----------------
__device__ __forceinline__ void resblock(float* P, float* A1, float* WB,
                                         const float* __restrict__ wt1, const float* __restrict__ b1,
                                         const float* __restrict__ wt2, const float* __restrict__ b2,
                                         int tx, int ty)
{
    __syncthreads();
    stage_f4(WB, wt1, 4096);
    __syncthreads();
    u64 acc[8][4];
    acc_bias128(acc, b1, tx);
    gemm_n128(P, WB, 128, acc, tx, ty);
    __syncthreads();
    #pragma unroll
    for (int u = 0; u < 8; u++) {
        int rs = (ty * 8 + u) * 128 + tx * 8;
        float2 v0 = upk2(acc[u][0]), v1 = upk2(acc[u][1]), v2 = upk2(acc[u][2]), v3 = upk2(acc[u][3]);
        *(float4*)(A1 + rs)     = make_float4(siluf(v0.x), siluf(v0.y), siluf(v1.x), siluf(v1.y));
        *(float4*)(A1 + rs + 4) = make_float4(siluf(v2.x), siluf(v2.y), siluf(v3.x), siluf(v3.y));
    }
    stage_f4(WB, wt2, 4096);
    __syncthreads();
    acc_bias128(acc, b2, tx);
    gemm_n128(A1, WB, 128, acc, tx, ty);
    #pragma unroll
    for (int u = 0; u < 8; u++) {
        int rs = (ty * 8 + u) * 128 + tx * 8;
        float4 p0 = *(const float4*)(P + rs);
        float4 p1 = *(const float4*)(P + rs + 4);
        float2 v0 = upk2(acc[u][0]), v1 = upk2(acc[u][1]), v2 = upk2(acc[u][2]), v3 = upk2(acc[u][3]);
        *(float4*)(P + rs)     = make_float4(p0.x + siluf(v0.x), p0.y + siluf(v0.y),
                                             p0.z + siluf(v1.x), p0.w + siluf(v1.y));
        *(float4*)(P + rs + 4) = make_float4(p1.x + siluf(v2.x), p1.y + siluf(v2.y),
                                             p1.z + siluf(v3.x), p1.w + siluf(v3.y));
    }
}

// ---------------- Kernel B: x_p2, ta GEMM, gather-mul, up-proj, residual tail, outputs ----------------
extern "C" __global__ void __launch_bounds__(NTHR, 1)
kernelB(const float* __restrict__ ta, const float* __restrict__ sbf0,
        const int* __restrict__ p_idx, const float* __restrict__ x1,
        const float* __restrict__ b_p2,
        const float* __restrict__ rb_b1, const float* __restrict__ rb_b2,
        const float* __restrict__ b_lin,
        const float* __restrict__ ra_b1, const float* __restrict__ ra_b2,
        float* __restrict__ out)
{
    extern __shared__ float sm[];
    float* A1 = sm;
    float* WB = sm + 16384;
    float* P  = sm + 32768;
    int tx = threadIdx.x & 15, ty = threadIdx.x >> 4;
    int r0 = blockIdx.x * TILE;

    u64 acc[8][4];

    // ---- x_p2 = silu(x1@Wp2 + b) -> P  (fused here: kills the g_xp2 gmem round-trip)
    stage_f4(A1, x1 + (size_t)r0 * 128, 4096);
    stage_f4(WB, g_wt + WT_P2, 4096);
    __syncthreads();
    acc_bias128(acc, b_p2, tx);
    gemm_n128(A1, WB, 128, acc, tx, ty);
    #pragma unroll
    for (int u = 0; u < 8; u++) {
        int rs = (ty * 8 + u) * 128 + tx * 8;
        float2 v0 = upk2(acc[u][0]), v1 = upk2(acc[u][1]), v2 = upk2(acc[u][2]), v3 = upk2(acc[u][3]);
        *(float4*)(P + rs)     = make_float4(siluf(v0.x), siluf(v0.y), siluf(v1.x), siluf(v1.y));
        *(float4*)(P + rs + 4) = make_float4(siluf(v2.x), siluf(v2.y), siluf(v3.x), siluf(v3.y));
    }

    // ---- ta_p = ta @ WtC  (K=294 in chunks 128/128/40(pad))
    u64 acc2[8][2];
    acc_zero64(acc2);
    const int k0s[3] = {0, 128, 256};
    const int kcs[3] = {128, 128, 40};
    const int kvs[3] = {128, 128, 38};
    for (int c = 0; c < 3; c++) {
        __syncthreads();                       // prior gemm reads of A1/WB done
        stage_ta(A1, ta + (size_t)r0 * 294 + k0s[c], kcs[c], kvs[c]);
        stage_f4(WB, g_wt + WT_TC + k0s[c] * 64, kcs[c] * 16);
        __syncthreads();
        gemm_n64(A1, WB, kcs[c], acc2, tx, ty);
    }
    __syncthreads();

    // ---- g = t[p_idx] * ta_p -> A1 cols 0..63
    #pragma unroll
    for (int u = 0; u < 8; u++) {
        int r = r0 + ty * 8 + u;
        int idx = p_idx[r];
        float4 g = *(const float4*)(g_t + (size_t)idx * 64 + tx * 4);
        float2 t0 = upk2(acc2[u][0]), t1 = upk2(acc2[u][1]);
        *(float4*)(A1 + (ty * 8 + u) * 128 + tx * 4) =
            make_float4(t0.x * g.x, t0.y * g.y, t1.x * g.z, t1.y * g.w);
    }
    stage_f4(WB, g_wt + WT_UP, 2048);
    __syncthreads();

    // ---- p1 = silu(g @ Wup) + x_p2(P)  (in place; thread owns its P cells)
    acc_zero128(acc);
    gemm_n128(A1, WB, 64, acc, tx, ty);
    #pragma unroll
    for (int u = 0; u < 8; u++) {
        int rs = (ty * 8 + u) * 128 + tx * 8;
        float4 x0 = *(const float4*)(P + rs);
        float4 x1v = *(const float4*)(P + rs + 4);
        float2 v0 = upk2(acc[u][0]), v1 = upk2(acc[u][1]), v2 = upk2(acc[u][2]), v3 = upk2(acc[u][3]);
        *(float4*)(P + rs)     = make_float4(x0.x + siluf(v0.x), x0.y + siluf(v0.y),
                                             x0.z + siluf(v1.x), x0.w + siluf(v1.y));
        *(float4*)(P + rs + 4) = make_float4(x1v.x + siluf(v2.x), x1v.y + siluf(v2.y),
                                             x1v.z + siluf(v3.x), x1v.w + siluf(v3.y));
    }

    // ---- res-before (1 block)
    resblock(P, A1, WB, g_wt + WT_RB1, rb_b1, g_wt + WT_RB2, rb_b2, tx, ty);

    // ---- p1 = silu(p1@Wlin + b) + x1
    __syncthreads();
    stage_f4(WB, g_wt + WT_LIN, 4096);
    __syncthreads();
    acc_bias128(acc, b_lin, tx);
    gemm_n128(P, WB, 128, acc, tx, ty);
    __syncthreads();   // FIX: cross-thread readers of P must finish before in-place write
    #pragma unroll
    for (int u = 0; u < 8; u++) {
        size_t rg = (size_t)(r0 + ty * 8 + u) * 128 + tx * 8;
        int rs = (ty * 8 + u) * 128 + tx * 8;
        float4 x0 = *(const float4*)(x1 + rg);
        float4 x1v = *(const float4*)(x1 + rg + 4);
        float2 v0 = upk2(acc[u][0]), v1 = upk2(acc[u][1]), v2 = upk2(acc[u][2]), v3 = upk2(acc[u][3]);
        *(float4*)(P + rs)     = make_float4(x0.x + siluf(v0.x), x0.y + siluf(v0.y),
                                             x0.z + siluf(v1.x), x0.w + siluf(v1.y));
        *(float4*)(P + rs + 4) = make_float4(x1v.x + siluf(v2.x), x1v.y + siluf(v2.y),
                                             x1v.z + siluf(v3.x), x1v.w + siluf(v3.y));
    }

    // ---- res-after (2 blocks)
    resblock(P, A1, WB, g_wt + WT_RA1,         ra_b1,       g_wt + WT_RA2,         ra_b2,       tx, ty);
    resblock(P, A1, WB, g_wt + WT_RA1 + 16384, ra_b1 + 128, g_wt + WT_RA2 + 16384, ra_b2 + 128, tx, ty);

    __syncthreads();
    // ---- write p1 (contiguous tile copy)
    {
        const float4* s = (const float4*)P;
        float4* d = (float4*)(out + (size_t)r0 * 128);
        for (int i = threadIdx.x; i < 4096; i += NTHR) d[i] = s[i];
    }
    // ---- p2 = (sbf0 @ Wsbf) * p1
    stage_sbf(A1, sbf0 + (size_t)r0 * 42);
    stage_f4(WB, g_wt + WT_SBF, 1408);
    __syncthreads();
    acc_zero128(acc);
    gemm_n128(A1, WB, 44, acc, tx, ty);
    float* out2 = out + (size_t)E_EDGES * 128;
    #pragma unroll
    for (int u = 0; u < 8; u++) {
        size_t rg = (size_t)(r0 + ty * 8 + u) * 128 + tx * 8;
        int rs = (ty * 8 + u) * 128 + tx * 8;
        float4 p0 = *(const float4*)(P + rs);
        float4 p1v = *(const float4*)(P + rs + 4);
        float2 v0 = upk2(acc[u][0]), v1 = upk2(acc[u][1]), v2 = upk2(acc[u][2]), v3 = upk2(acc[u][3]);
        *(float4*)(out2 + rg)     = make_float4(v0.x * p0.x, v0.y * p0.y, v1.x * p0.z, v1.y * p0.w);
        *(float4*)(out2 + rg + 4) = make_float4(v2.x * p1v.x, v2.y * p1v.y, v3.x * p1v.z, v3.y * p1v.w);
    }
}

// ---------------- launch ----------------
extern "C" void kernel_launch(void* const* d_in, const int* in_sizes, int n_in,
                              void* d_out, int out_size)
{
    const float* x1     = (const float*)d_in[0];
    const float* sbf0   = (const float*)d_in[1];
    const float* ta     = (const float*)d_in[2];
    const int*   p_idx  = (const int*)  d_in[3];
    const float* w_p2   = (const float*)d_in[4];
    const float* b_p2   = (const float*)d_in[5];
    const float* w_p4   = (const float*)d_in[6];
    const float* b_p4   = (const float*)d_in[7];
    const float* w_sbf1 = (const float*)d_in[8];
    const float* w_sbf2 = (const float*)d_in[9];
    const float* w_t1   = (const float*)d_in[10];
    const float* w_t2   = (const float*)d_in[11];
    const float* w_down = (const float*)d_in[12];
    const float* w_up   = (const float*)d_in[13];
    const float* rb_w1  = (const float*)d_in[14];
    const float* rb_b1  = (const float*)d_in[15];
    const float* rb_w2  = (const float*)d_in[16];
    const float* rb_b2  = (const float*)d_in[17];
    const float* w_lin  = (const float*)d_in[18];
    const float* b_lin  = (const float*)d_in[19];
    const float* ra_w1  = (const float*)d_in[20];
    const float* ra_b1  = (const float*)d_in[21];
    const float* ra_w2  = (const float*)d_in[22];
    const float* ra_b2  = (const float*)d_in[23];
    const float* w_sbf  = (const float*)d_in[24];
    float* out = (float*)d_out;

    const int SMEM = 3 * 16384 * (int)sizeof(float); // 192 KB
    cudaFuncSetAttribute(kernelA, cudaFuncAttributeMaxDynamicSharedMemorySize, SMEM);
    cudaFuncSetAttribute(kernelB, cudaFuncAttributeMaxDynamicSharedMemorySize, SMEM);

    setup_kernel<<<128, 256>>>(w_p2, w_p4, w_sbf1, w_sbf2, w_t1, w_t2, w_down, w_up,
                               rb_w1, rb_w2, w_lin, ra_w1, ra_w2, w_sbf);
    kernelA<<<E_EDGES / TILE, NTHR, SMEM>>>(x1, sbf0, b_p4);
    kernelB<<<E_EDGES / TILE, NTHR, SMEM>>>(ta, sbf0, p_idx, x1, b_p2,
                                            rb_b1, rb_b2, b_lin, ra_b1, ra_b2, out);
}

// round 11
// speedup vs baseline: 2.2796x; 2.2796x over previous
#include <cuda_runtime.h>
#include <cuda_bf16.h>

typedef unsigned int u32;

#define E_EDGES 400000
#define NTHR 256
#define ASTR 136
#define WSTR 136
#define PSTR 130

// smem byte offsets
#define A_HI 0
#define A_LO 34816
#define W_HI 69632
#define W_LO 104448
#define P_OFF 139264
#define SMEM_TOTAL (P_OFF + 128*PSTR*4)   // 205824 B

enum { WE_P2=0, WE_P4, WE_RB1, WE_RB2, WE_LIN, WE_RA1A, WE_RA2A, WE_RA1B, WE_RA2B,
       WE_SBFC, WE_SBF, WE_DOWN, WE_UP, WE_TC0, WE_TC1, WE_TC2, WE_COUNT };

__device__ __align__(16) __nv_bfloat16 g_wb[WE_COUNT * 32768];
__device__ float g_t[(size_t)E_EDGES * 64];

__device__ __forceinline__ u32 smem_u32(const void* p) {
    u32 a; asm("{ .reg .u64 t; cvta.to.shared.u64 t, %1; cvt.u32.u64 %0, t; }" : "=r"(a) : "l"(p));
    return a;
}
__device__ __forceinline__ float siluf(float x) { return __fdividef(x, 1.0f + __expf(-x)); }

__device__ __forceinline__ void ldmA(u32 addr, u32 &r0, u32 &r1, u32 &r2, u32 &r3) {
    asm volatile("ldmatrix.sync.aligned.m8n8.x4.shared.b16 {%0,%1,%2,%3}, [%4];"
                 : "=r"(r0), "=r"(r1), "=r"(r2), "=r"(r3) : "r"(addr));
}
__device__ __forceinline__ void ldmBT(u32 addr, u32 &r0, u32 &r1) {
    asm volatile("ldmatrix.sync.aligned.m8n8.x2.trans.shared.b16 {%0,%1}, [%2];"
                 : "=r"(r0), "=r"(r1) : "r"(addr));
}
__device__ __forceinline__ void mma16816(float* c, u32 a0, u32 a1, u32 a2, u32 a3, u32 b0, u32 b1) {
    asm volatile("mma.sync.aligned.m16n8k16.row.col.f32.bf16.bf16.f32 "
                 "{%0,%1,%2,%3},{%4,%5,%6,%7},{%8,%9},{%0,%1,%2,%3};"
                 : "+f"(c[0]), "+f"(c[1]), "+f"(c[2]), "+f"(c[3])
                 : "r"(a0), "r"(a1), "r"(a2), "r"(a3), "r"(b0), "r"(b1));
}
__device__ __forceinline__ void za(float* a) {
    #pragma unroll
    for (int i = 0; i < 64; i++) a[i] = 0.f;
}

// ---------------- setup: fold, split hi/lo, store [K][N] k-major ----------------
__global__ void setup_kernel(
    const float* __restrict__ w_p2, const float* __restrict__ w_p4,
    const float* __restrict__ w_sbf1, const float* __restrict__ w_sbf2,
    const float* __restrict__ w_t1, const float* __restrict__ w_t2,
    const float* __restrict__ w_down, const float* __restrict__ w_up,
    const float* __restrict__ rb_w1, const float* __restrict__ rb_w2,
    const float* __restrict__ w_lin,
    const float* __restrict__ ra_w1, const float* __restrict__ ra_w2,
    const float* __restrict__ w_sbf)
{
    int tid = blockIdx.x * blockDim.x + threadIdx.x;
    int nt = gridDim.x * blockDim.x;
    const float* Wsrc[9] = { w_p2, w_p4, rb_w1, rb_w2, w_lin, ra_w1, ra_w2, ra_w1 + 16384, ra_w2 + 16384 };
    const int Went[9] = { WE_P2, WE_P4, WE_RB1, WE_RB2, WE_LIN, WE_RA1A, WE_RA2A, WE_RA1B, WE_RA2B };
    for (int e = 0; e < 9; e++) {
        __nv_bfloat16* dst = g_wb + Went[e] * 32768;
        for (int i = tid; i < 16384; i += nt) {   // i = k*128 + n
            int k = i >> 7, n = i & 127;
            float v = Wsrc[e][n * 128 + k];
            __nv_bfloat16 h = __float2bfloat16(v);
            dst[i] = h; dst[16384 + i] = __float2bfloat16(v - __bfloat162float(h));
        }
    }
    {   // SBFC: K=48(42 valid), N=128 folded
        __nv_bfloat16* dst = g_wb + WE_SBFC * 32768;
        for (int i = tid; i < 48 * 128; i += nt) {
            int k = i >> 7, n = i & 127; float v = 0.f;
            if (k < 42) {
                for (int b = 0; b < 8; b++) v += w_sbf2[n * 8 + b] * w_sbf1[b * 42 + k];
            }
            __nv_bfloat16 h = __float2bfloat16(v);
            dst[i] = h; dst[16384 + i] = __float2bfloat16(v - __bfloat162float(h));
        }
    }
    {   // SBF: K=48, N=128
        __nv_bfloat16* dst = g_wb + WE_SBF * 32768;
        for (int i = tid; i < 48 * 128; i += nt) {
            int k = i >> 7, n = i & 127;
            float v = (k < 42) ? w_sbf[n * 42 + k] : 0.f;
            __nv_bfloat16 h = __float2bfloat16(v);
            dst[i] = h; dst[16384 + i] = __float2bfloat16(v - __bfloat162float(h));
        }
    }
    {   // DOWN: K=128, N=64
        __nv_bfloat16* dst = g_wb + WE_DOWN * 32768;
        for (int i = tid; i < 128 * 64; i += nt) {
            int k = i >> 6, n = i & 63;
            float v = w_down[n * 128 + k];
            __nv_bfloat16 h = __float2bfloat16(v);
            dst[i] = h; dst[16384 + i] = __float2bfloat16(v - __bfloat162float(h));
        }
    }
    {   // UP: K=64, N=128
        __nv_bfloat16* dst = g_wb + WE_UP * 32768;
        for (int i = tid; i < 64 * 128; i += nt) {
            int k = i >> 7, n = i & 127;
            float v = w_up[n * 64 + k];
            __nv_bfloat16 h = __float2bfloat16(v);
            dst[i] = h; dst[16384 + i] = __float2bfloat16(v - __bfloat162float(h));
        }
    }
    for (int c = 0; c < 3; c++) {   // TC: N=64, K 128/128/48, folded
        int kp = (c < 2) ? 128 : 48;
        __nv_bfloat16* dst = g_wb + (WE_TC0 + c) * 32768;
        for (int i = tid; i < kp * 64; i += nt) {
            int k = i >> 6, n = i & 63, kg = c * 128 + k;
            float v = 0.f;
            if (kg < 294) {
                for (int b = 0; b < 8; b++) v += w_t2[n * 8 + b] * w_t1[b * 294 + kg];
            }
            __nv_bfloat16 h = __float2bfloat16(v);
            dst[i] = h; dst[16384 + i] = __float2bfloat16(v - __bfloat162float(h));
        }
    }
}

// ---------------- staging ----------------
__device__ __forceinline__ void stageW(char* sm, int entry, int K, int N) {
    const __nv_bfloat16* src = g_wb + entry * 32768;
    int nb8 = N >> 3, tot = K * nb8;
    for (int i = threadIdx.x; i < tot; i += NTHR) {
        int k = i / nb8, nb = i - k * nb8;
        float4 h = *(const float4*)(src + k * N + nb * 8);
        float4 lo = *(const float4*)(src + 16384 + k * N + nb * 8);
        *(float4*)(sm + W_HI + (k * WSTR + nb * 8) * 2) = h;
        *(float4*)(sm + W_LO + (k * WSTR + nb * 8) * 2) = lo;
    }
}
__device__ __forceinline__ void splitA(char* sm, int rr, int col, float a, float b) {
    __nv_bfloat162 h = __floats2bfloat162_rn(a, b);
    __nv_bfloat162 lo = __floats2bfloat162_rn(a - __bfloat162float(h.x), b - __bfloat162float(h.y));
    int off = (rr * ASTR + col) * 2;
    *(__nv_bfloat162*)(sm + A_HI + off) = h;
    *(__nv_bfloat162*)(sm + A_LO + off) = lo;
}
__device__ __forceinline__ void stage_split(char* sm, const float* __restrict__ src,
                                            int rstride, int kvalid, int npairs) {
    for (int i = threadIdx.x; i < 128 * npairs; i += NTHR) {
        int rr = i / npairs, jp = i - rr * npairs;
        float2 xv = (2 * jp < kvalid) ? *(const float2*)(src + (size_t)rr * rstride + 2 * jp)
                                      : make_float2(0.f, 0.f);
        splitA(sm, rr, 2 * jp, xv.x, xv.y);
    }
}

// ---------------- warp GEMM: 3-pass bf16 split, fragments in regs ----------------
template<int NB>
__device__ __forceinline__ void wgemm(u32 smu, int nk, float* acc, int mrow, int ncol, int lane) {
    u32 aoff = (u32)((mrow + (lane & 15)) * ASTR + ((lane >> 4) << 3)) * 2;
    u32 boff = (u32)((lane & 15) * WSTR + ncol) * 2;
    #pragma unroll
    for (int p = 0; p < 3; p++) {
        u32 aBase = smu + (p == 2 ? A_LO : A_HI) + aoff;
        u32 bBase = smu + (p == 1 ? W_LO : W_HI) + boff;
        for (int kc = 0; kc < nk; kc++) {
            u32 a0, a1, a2, a3, a4, a5, a6, a7;
            u32 aA = aBase + kc * 32;
            ldmA(aA, a0, a1, a2, a3);
            ldmA(aA + 16 * ASTR * 2, a4, a5, a6, a7);
            u32 bA = bBase + kc * 16 * WSTR * 2;
            #pragma unroll
            for (int nb = 0; nb < NB; nb++) {
                u32 b0, b1; ldmBT(bA + nb * 16, b0, b1);
                mma16816(acc + nb * 4, a0, a1, a2, a3, b0, b1);
                mma16816(acc + (NB + nb) * 4, a4, a5, a6, a7, b0, b1);
            }
        }
    }
}

// epilogue iteration via lambda (comma-safe, fully inlined)
template<int NB, typename F>
__device__ __forceinline__ void epi(float* acc, int mrow, int ncol, int lane, F f) {
    #pragma unroll
    for (int mt = 0; mt < 2; mt++)
    #pragma unroll
    for (int nb = 0; nb < NB; nb++) {
        int col = ncol + nb * 8 + (lane & 3) * 2;
        #pragma unroll
        for (int ri = 0; ri < 2; ri++) {
            int rr = mrow + mt * 16 + (lane >> 2) + ri * 8;
            float* cc = acc + (mt * NB + nb) * 4 + ri * 2;
            f(rr, col, cc);
        }
    }
}

// ---------------- Kernel A: g_t = silu((silu(x1@Wp4+b)*sbf)@Wdown) ----------------
extern "C" __global__ void __launch_bounds__(NTHR, 1)
kernelA(const float* __restrict__ x1, const float* __restrict__ sbf0,
        const float* __restrict__ b_p4)
{
    extern __shared__ char sm[];
    u32 smu = smem_u32(sm);
    int tid = threadIdx.x, w = tid >> 5, lane = tid & 31;
    int mrow = (w & 3) * 32, wn = w >> 2;
    int r0 = blockIdx.x * 128;
    float* P = (float*)(sm + P_OFF);
    float acc[64];

    stage_split(sm, x1 + (size_t)r0 * 128, 128, 128, 64);
    stageW(sm, WE_P4, 128, 128);
    __syncthreads();
    za(acc); wgemm<8>(smu, 8, acc, mrow, wn * 64, lane);
    __syncthreads();
    epi<8>(acc, mrow, wn * 64, lane, [&](int rr, int col, float* cc) {
        float2 bb = *(const float2*)(b_p4 + col);
        *(float2*)(P + rr * PSTR + col) = make_float2(siluf(cc[0] + bb.x), siluf(cc[1] + bb.y));
    });
    __syncthreads();

    stage_split(sm, sbf0 + (size_t)r0 * 42, 42, 42, 24);
    stageW(sm, WE_SBFC, 48, 128);
    __syncthreads();
    za(acc); wgemm<8>(smu, 3, acc, mrow, wn * 64, lane);
    __syncthreads();
    epi<8>(acc, mrow, wn * 64, lane, [&](int rr, int col, float* cc) {
        float2 pv = *(float2*)(P + rr * PSTR + col);
        splitA(sm, rr, col, cc[0] * pv.x, cc[1] * pv.y);
    });
    stageW(sm, WE_DOWN, 128, 64);
    __syncthreads();
    za(acc); wgemm<4>(smu, 8, acc, mrow, wn * 32, lane);
    epi<4>(acc, mrow, wn * 32, lane, [&](int rr, int col, float* cc) {
        *(float2*)(g_t + (size_t)(r0 + rr) * 64 + col) = make_float2(siluf(cc[0]), siluf(cc[1]));
    });
}

// ---------------- Kernel B: full tail ----------------
extern "C" __global__ void __launch_bounds__(NTHR, 1)
kernelB(const float* __restrict__ ta, const float* __restrict__ sbf0,
        const int* __restrict__ p_idx, const float* __restrict__ x1,
        const float* __restrict__ b_p2,
        const float* __restrict__ rb_b1, const float* __restrict__ rb_b2,
        const float* __restrict__ b_lin,
        const float* __restrict__ ra_b1, const float* __restrict__ ra_b2,
        float* __restrict__ out)
{
    extern __shared__ char sm[];
    u32 smu = smem_u32(sm);
    int tid = threadIdx.x, w = tid >> 5, lane = tid & 31;
    int mrow = (w & 3) * 32, wn = w >> 2;
    int r0 = blockIdx.x * 128;
    float* P = (float*)(sm + P_OFF);
    float acc[64];

    // G1: x_p2 = silu(x1@Wp2 + b) -> P
    stage_split(sm, x1 + (size_t)r0 * 128, 128, 128, 64);
    stageW(sm, WE_P2, 128, 128);
    __syncthreads();
    za(acc); wgemm<8>(smu, 8, acc, mrow, wn * 64, lane);
    __syncthreads();
    epi<8>(acc, mrow, wn * 64, lane, [&](int rr, int col, float* cc) {
        float2 bb = *(const float2*)(b_p2 + col);
        *(float2*)(P + rr * PSTR + col) = make_float2(siluf(cc[0] + bb.x), siluf(cc[1] + bb.y));
    });
    __syncthreads();

    // G2: ta_p = ta@WtC (3 chunks, reg-accumulated), then gather-mul -> A(K=64)
    za(acc);
    {
        const int k0s[3] = {0, 128, 256};
        const int kvs[3] = {128, 128, 38};
        const int nps[3] = {64, 64, 24};
        const int Ks[3]  = {128, 128, 48};
        const int nks[3] = {8, 8, 3};
        for (int c = 0; c < 3; c++) {
            stage_split(sm, ta + (size_t)r0 * 294 + k0s[c], 294, kvs[c], nps[c]);
            stageW(sm, WE_TC0 + c, Ks[c], 64);
            __syncthreads();
            wgemm<4>(smu, nks[c], acc, mrow, wn * 32, lane);
            __syncthreads();
        }
    }
    epi<4>(acc, mrow, wn * 32, lane, [&](int rr, int col, float* cc) {
        int idx = p_idx[r0 + rr];
        float2 tv = *(const float2*)(g_t + (size_t)idx * 64 + col);
        splitA(sm, rr, col, cc[0] * tv.x, cc[1] * tv.y);
    });

    // G3: p1 = silu(g@Wup) + x_p2 -> P, A
    stageW(sm, WE_UP, 64, 128);
    __syncthreads();
    za(acc); wgemm<8>(smu, 4, acc, mrow, wn * 64, lane);
    __syncthreads();
    epi<8>(acc, mrow, wn * 64, lane, [&](int rr, int col, float* cc) {
        float* pp = P + rr * PSTR + col;
        float v0 = siluf(cc[0]) + pp[0];
        float v1 = siluf(cc[1]) + pp[1];
        pp[0] = v0; pp[1] = v1;
        splitA(sm, rr, col, v0, v1);
    });

    // G4..G9: RB1, RB2, LIN, RA1A, RA2A, RA1B
    const int ent1[6] = { WE_RB1, WE_RB2, WE_LIN, WE_RA1A, WE_RA2A, WE_RA1B };
    const float* bs1[6] = { rb_b1, rb_b2, b_lin, ra_b1, ra_b2, ra_b1 + 128 };
    #pragma unroll 1
    for (int s = 0; s < 6; s++) {
        stageW(sm, ent1[s], 128, 128);
        __syncthreads();
        za(acc); wgemm<8>(smu, 8, acc, mrow, wn * 64, lane);
        __syncthreads();
        const float* bb_ = bs1[s];
        if (s == 0 || s == 3 || s == 5) {           // first half of res block: A = silu(v+b)
            epi<8>(acc, mrow, wn * 64, lane, [&](int rr, int col, float* cc) {
                float2 bb = *(const float2*)(bb_ + col);
                splitA(sm, rr, col, siluf(cc[0] + bb.x), siluf(cc[1] + bb.y));
            });
        } else if (s == 1 || s == 4) {              // second half: P += silu(v+b); A = P
            epi<8>(acc, mrow, wn * 64, lane, [&](int rr, int col, float* cc) {
                float2 bb = *(const float2*)(bb_ + col);
                float* pp = P + rr * PSTR + col;
                float v0 = pp[0] + siluf(cc[0] + bb.x);
                float v1 = pp[1] + siluf(cc[1] + bb.y);
                pp[0] = v0; pp[1] = v1;
                splitA(sm, rr, col, v0, v1);
            });
        } else {                                    // lin: P = silu(v+b) + x1; A = P
            epi<8>(acc, mrow, wn * 64, lane, [&](int rr, int col, float* cc) {
                float2 bb = *(const float2*)(bb_ + col);
                float2 xv = *(const float2*)(x1 + (size_t)(r0 + rr) * 128 + col);
                float* pp = P + rr * PSTR + col;
                float v0 = siluf(cc[0] + bb.x) + xv.x;
                float v1 = siluf(cc[1] + bb.y) + xv.y;
                pp[0] = v0; pp[1] = v1;
                splitA(sm, rr, col, v0, v1);
            });
        }
    }

    // G10: RA2B — p1 final: P += silu(v+b); write out p1
    stageW(sm, WE_RA2B, 128, 128);
    __syncthreads();
    za(acc); wgemm<8>(smu, 8, acc, mrow, wn * 64, lane);
    __syncthreads();
    epi<8>(acc, mrow, wn * 64, lane, [&](int rr, int col, float* cc) {
        float2 bb = *(const float2*)(ra_b2 + 128 + col);
        float* pp = P + rr * PSTR + col;
        float v0 = pp[0] + siluf(cc[0] + bb.x);
        float v1 = pp[1] + siluf(cc[1] + bb.y);
        pp[0] = v0; pp[1] = v1;
        *(float2*)(out + (size_t)(r0 + rr) * 128 + col) = make_float2(v0, v1);
    });
    __syncthreads();

    // G11: p2 = (sbf0@Wsbf) * p1
    stage_split(sm, sbf0 + (size_t)r0 * 42, 42, 42, 24);
    stageW(sm, WE_SBF, 48, 128);
    __syncthreads();
    za(acc); wgemm<8>(smu, 3, acc, mrow, wn * 64, lane);
    float* out2 = out + (size_t)E_EDGES * 128;
    epi<8>(acc, mrow, wn * 64, lane, [&](int rr, int col, float* cc) {
        float* pp = P + rr * PSTR + col;
        *(float2*)(out2 + (size_t)(r0 + rr) * 128 + col) = make_float2(cc[0] * pp[0], cc[1] * pp[1]);
    });
}

// ---------------- launch ----------------
extern "C" void kernel_launch(void* const* d_in, const int* in_sizes, int n_in,
                              void* d_out, int out_size)
{
    const float* x1     = (const float*)d_in[0];
    const float* sbf0   = (const float*)d_in[1];
    const float* ta     = (const float*)d_in[2];
    const int*   p_idx  = (const int*)  d_in[3];
    const float* w_p2   = (const float*)d_in[4];
    const float* b_p2   = (const float*)d_in[5];
    const float* w_p4   = (const float*)d_in[6];
    const float* b_p4   = (const float*)d_in[7];
    const float* w_sbf1 = (const float*)d_in[8];
    const float* w_sbf2 = (const float*)d_in[9];
    const float* w_t1   = (const float*)d_in[10];
    const float* w_t2   = (const float*)d_in[11];
    const float* w_down = (const float*)d_in[12];
    const float* w_up   = (const float*)d_in[13];
    const float* rb_w1  = (const float*)d_in[14];
    const float* rb_b1  = (const float*)d_in[15];
    const float* rb_w2  = (const float*)d_in[16];
    const float* rb_b2  = (const float*)d_in[17];
    const float* w_lin  = (const float*)d_in[18];
    const float* b_lin  = (const float*)d_in[19];
    const float* ra_w1  = (const float*)d_in[20];
    const float* ra_b1  = (const float*)d_in[21];
    const float* ra_w2  = (const float*)d_in[22];
    const float* ra_b2  = (const float*)d_in[23];
    const float* w_sbf  = (const float*)d_in[24];
    float* out = (float*)d_out;

    cudaFuncSetAttribute(kernelA, cudaFuncAttributeMaxDynamicSharedMemorySize, SMEM_TOTAL);
    cudaFuncSetAttribute(kernelB, cudaFuncAttributeMaxDynamicSharedMemorySize, SMEM_TOTAL);

    setup_kernel<<<128, 256>>>(w_p2, w_p4, w_sbf1, w_sbf2, w_t1, w_t2, w_down, w_up,
                               rb_w1, rb_w2, w_lin, ra_w1, ra_w2, w_sbf);
    kernelA<<<E_EDGES / 128, NTHR, SMEM_TOTAL>>>(x1, sbf0, b_p4);
    kernelB<<<E_EDGES / 128, NTHR, SMEM_TOTAL>>>(ta, sbf0, p_idx, x1, b_p2,
                                                 rb_b1, rb_b2, b_lin, ra_b1, ra_b2, out);
}

// round 13
// speedup vs baseline: 2.6567x; 1.1654x over previous
#include <cuda_runtime.h>
#include <cuda_bf16.h>

typedef unsigned int u32;

#define E_EDGES 400000
#define NTHR 512
#define ASTR 136
#define WSTR 136
#define PSTR 130

// smem byte offsets
#define A_HI 0
#define A_LO 34816
#define W_HI 69632
#define W_LO 104448
#define P_OFF 139264
#define SMEM_TOTAL (P_OFF + 128*PSTR*4)   // 205824 B

enum { WE_P2=0, WE_P4, WE_RB1, WE_RB2, WE_LIN, WE_RA1A, WE_RA2A, WE_RA1B, WE_RA2B,
       WE_SBFC, WE_SBF, WE_DOWN, WE_UP, WE_TC0, WE_TC1, WE_TC2, WE_COUNT };

// each entry is the exact smem W image: hi at +0 (K rows x WSTR stride), lo at +17408 elems
#define WENT 34816
__device__ __align__(16) __nv_bfloat16 g_wb[WE_COUNT * WENT];
__device__ float g_t[(size_t)E_EDGES * 64];

__device__ __forceinline__ u32 smem_u32(const void* p) {
    u32 a; asm("{ .reg .u64 t; cvta.to.shared.u64 t, %1; cvt.u32.u64 %0, t; }" : "=r"(a) : "l"(p));
    return a;
}
__device__ __forceinline__ float siluf(float x) { return __fdividef(x, 1.0f + __expf(-x)); }

__device__ __forceinline__ void ldmA(u32 addr, u32 &r0, u32 &r1, u32 &r2, u32 &r3) {
    asm volatile("ldmatrix.sync.aligned.m8n8.x4.shared.b16 {%0,%1,%2,%3}, [%4];"
                 : "=r"(r0), "=r"(r1), "=r"(r2), "=r"(r3) : "r"(addr));
}
__device__ __forceinline__ void ldmB4(u32 addr, u32 &r0, u32 &r1, u32 &r2, u32 &r3) {
    asm volatile("ldmatrix.sync.aligned.m8n8.x4.trans.shared.b16 {%0,%1,%2,%3}, [%2+0];"
                 : "=r"(r0), "=r"(r1), "=r"(r2), "=r"(r3) : "r"(addr));
}
__device__ __forceinline__ void ldmB4f(u32 addr, u32 &r0, u32 &r1, u32 &r2, u32 &r3) {
    asm volatile("ldmatrix.sync.aligned.m8n8.x4.trans.shared.b16 {%0,%1,%2,%3}, [%4];"
                 : "=r"(r0), "=r"(r1), "=r"(r2), "=r"(r3) : "r"(addr));
}
__device__ __forceinline__ void mma16816(float* c, u32 a0, u32 a1, u32 a2, u32 a3, u32 b0, u32 b1) {
    asm volatile("mma.sync.aligned.m16n8k16.row.col.f32.bf16.bf16.f32 "
                 "{%0,%1,%2,%3},{%4,%5,%6,%7},{%8,%9},{%0,%1,%2,%3};"
                 : "+f"(c[0]), "+f"(c[1]), "+f"(c[2]), "+f"(c[3])
                 : "r"(a0), "r"(a1), "r"(a2), "r"(a3), "r"(b0), "r"(b1));
}
template<int N>
__device__ __forceinline__ void za(float* a) {
    #pragma unroll
    for (int i = 0; i < N; i++) a[i] = 0.f;
}
__device__ __forceinline__ void cpasync16(u32 sa, const void* ga) {
    asm volatile("cp.async.cg.shared.global [%0], [%1], 16;" :: "r"(sa), "l"(ga) : "memory");
}
#define CP_COMMIT() asm volatile("cp.async.commit_group;" ::: "memory")
#define CP_WAIT()   asm volatile("cp.async.wait_group 0;" ::: "memory")

// ---------------- setup: fold, split hi/lo, store smem-image layout ----------------
__global__ void setup_kernel(
    const float* __restrict__ w_p2, const float* __restrict__ w_p4,
    const float* __restrict__ w_sbf1, const float* __restrict__ w_sbf2,
    const float* __restrict__ w_t1, const float* __restrict__ w_t2,
    const float* __restrict__ w_down, const float* __restrict__ w_up,
    const float* __restrict__ rb_w1, const float* __restrict__ rb_w2,
    const float* __restrict__ w_lin,
    const float* __restrict__ ra_w1, const float* __restrict__ ra_w2,
    const float* __restrict__ w_sbf)
{
    int tid = blockIdx.x * blockDim.x + threadIdx.x;
    int nt = gridDim.x * blockDim.x;
    const float* Wsrc[9] = { w_p2, w_p4, rb_w1, rb_w2, w_lin, ra_w1, ra_w2, ra_w1 + 16384, ra_w2 + 16384 };
    const int Went[9] = { WE_P2, WE_P4, WE_RB1, WE_RB2, WE_LIN, WE_RA1A, WE_RA2A, WE_RA1B, WE_RA2B };
    for (int e = 0; e < 9; e++) {
        __nv_bfloat16* dst = g_wb + Went[e] * WENT;
        for (int i = tid; i < 16384; i += nt) {   // i = k*128 + n
            int k = i >> 7, n = i & 127;
            float v = Wsrc[e][n * 128 + k];
            __nv_bfloat16 h = __float2bfloat16(v);
            int o = k * WSTR + n;
            dst[o] = h; dst[17408 + o] = __float2bfloat16(v - __bfloat162float(h));
        }
    }
    {   // SBFC: K=48(42 valid), N=128 folded
        __nv_bfloat16* dst = g_wb + WE_SBFC * WENT;
        for (int i = tid; i < 48 * 128; i += nt) {
            int k = i >> 7, n = i & 127; float v = 0.f;
            if (k < 42) {
                for (int b = 0; b < 8; b++) v += w_sbf2[n * 8 + b] * w_sbf1[b * 42 + k];
            }
            __nv_bfloat16 h = __float2bfloat16(v);
            int o = k * WSTR + n;
            dst[o] = h; dst[17408 + o] = __float2bfloat16(v - __bfloat162float(h));
        }
    }
    {   // SBF: K=48, N=128
        __nv_bfloat16* dst = g_wb + WE_SBF * WENT;
        for (int i = tid; i < 48 * 128; i += nt) {
            int k = i >> 7, n = i & 127;
            float v = (k < 42) ? w_sbf[n * 42 + k] : 0.f;
            __nv_bfloat16 h = __float2bfloat16(v);
            int o = k * WSTR + n;
            dst[o] = h; dst[17408 + o] = __float2bfloat16(v - __bfloat162float(h));
        }
    }
    {   // DOWN: K=128, N=64
        __nv_bfloat16* dst = g_wb + WE_DOWN * WENT;
        for (int i = tid; i < 128 * 64; i += nt) {
            int k = i >> 6, n = i & 63;
            float v = w_down[n * 128 + k];
            __nv_bfloat16 h = __float2bfloat16(v);
            int o = k * WSTR + n;
            dst[o] = h; dst[17408 + o] = __float2bfloat16(v - __bfloat162float(h));
        }
    }
    {   // UP: K=64, N=128
        __nv_bfloat16* dst = g_wb + WE_UP * WENT;
        for (int i = tid; i < 64 * 128; i += nt) {
            int k = i >> 7, n = i & 127;
            float v = w_up[n * 64 + k];
            __nv_bfloat16 h = __float2bfloat16(v);
            int o = k * WSTR + n;
            dst[o] = h; dst[17408 + o] = __float2bfloat16(v - __bfloat162float(h));
        }
    }
    for (int c = 0; c < 3; c++) {   // TC: N=64, K 128/128/48, folded
        int kp = (c < 2) ? 128 : 48;
        __nv_bfloat16* dst = g_wb + (WE_TC0 + c) * WENT;
        for (int i = tid; i < kp * 64; i += nt) {
            int k = i >> 6, n = i & 63, kg = c * 128 + k;
            float v = 0.f;
            if (kg < 294) {
                for (int b = 0; b < 8; b++) v += w_t2[n * 8 + b] * w_t1[b * 294 + kg];
            }
            __nv_bfloat16 h = __float2bfloat16(v);
            int o = k * WSTR + n;
            dst[o] = h; dst[17408 + o] = __float2bfloat16(v - __bfloat162float(h));
        }
    }
}

// ---------------- staging ----------------
// async flat copy of the pre-built W image (hi + lo); overlapped with epilogue
__device__ __forceinline__ void stageW_async(u32 smu, int entry, int K) {
    const char* src = (const char*)(g_wb + entry * WENT);
    int nbytes = K * (WSTR * 2);
    for (int i = threadIdx.x * 16; i < nbytes; i += NTHR * 16) {
        cpasync16(smu + W_HI + i, src + i);
        cpasync16(smu + W_LO + i, src + 34816 + i);
    }
    CP_COMMIT();
}
__device__ __forceinline__ void splitA(char* sm, int rr, int col, float a, float b) {
    __nv_bfloat162 h = __floats2bfloat162_rn(a, b);
    __nv_bfloat162 lo = __floats2bfloat162_rn(a - __bfloat162float(h.x), b - __bfloat162float(h.y));
    int off = (rr * ASTR + col) * 2;
    *(__nv_bfloat162*)(sm + A_HI + off) = h;
    *(__nv_bfloat162*)(sm + A_LO + off) = lo;
}
__device__ __forceinline__ void stage_split(char* sm, const float* __restrict__ src,
                                            int rstride, int kvalid, int npairs) {
    for (int i = threadIdx.x; i < 128 * npairs; i += NTHR) {
        int rr = i / npairs, jp = i - rr * npairs;
        float2 xv = (2 * jp < kvalid) ? *(const float2*)(src + (size_t)rr * rstride + 2 * jp)
                                      : make_float2(0.f, 0.f);
        splitA(sm, rr, 2 * jp, xv.x, xv.y);
    }
}

// ---------------- warp GEMM: 3-pass bf16 split; 16 warps, 32x32 (or 32x16) each ----------------
template<int NB>
__device__ __forceinline__ void wgemm(u32 smu, int nk, float* acc, int mrow, int ncol, int lane) {
    u32 aoff = (u32)((mrow + (lane & 15)) * ASTR + ((lane >> 4) << 3)) * 2;
    u32 boff = (u32)((lane & 15) * WSTR + ncol + ((lane >> 4) << 3)) * 2;
    #pragma unroll
    for (int p = 0; p < 3; p++) {
        u32 aBase = smu + (p == 2 ? A_LO : A_HI) + aoff;
        u32 bBase = smu + (p == 1 ? W_LO : W_HI) + boff;
        for (int kc = 0; kc < nk; kc++) {
            u32 a0, a1, a2, a3, a4, a5, a6, a7;
            u32 aA = aBase + kc * 32;
            ldmA(aA, a0, a1, a2, a3);
            ldmA(aA + 16 * ASTR * 2, a4, a5, a6, a7);
            u32 bA = bBase + kc * 16 * WSTR * 2;
            #pragma unroll
            for (int nb2 = 0; nb2 < NB / 2; nb2++) {
                u32 b0, b1, b2, b3;
                ldmB4f(bA + nb2 * 32, b0, b1, b2, b3);
                mma16816(acc + nb2 * 8,              a0, a1, a2, a3, b0, b1);
                mma16816(acc + nb2 * 8 + 4,          a0, a1, a2, a3, b2, b3);
                mma16816(acc + (NB + nb2 * 2) * 4,   a4, a5, a6, a7, b0, b1);
                mma16816(acc + (NB + nb2 * 2 + 1) * 4, a4, a5, a6, a7, b2, b3);
            }
        }
    }
}

// epilogue iteration via lambda
template<int NB, typename F>
__device__ __forceinline__ void epi(float* acc, int mrow, int ncol, int lane, F f) {
    #pragma unroll
    for (int mt = 0; mt < 2; mt++)
    #pragma unroll
    for (int nb = 0; nb < NB; nb++) {
        int col = ncol + nb * 8 + (lane & 3) * 2;
        #pragma unroll
        for (int ri = 0; ri < 2; ri++) {
            int rr = mrow + mt * 16 + (lane >> 2) + ri * 8;
            float* cc = acc + (mt * NB + nb) * 4 + ri * 2;
            f(rr, col, cc);
        }
    }
}

// ---------------- Kernel A: g_t = silu((silu(x1@Wp4+b)*sbf)@Wdown) ----------------
extern "C" __global__ void __launch_bounds__(NTHR, 1)
kernelA(const float* __restrict__ x1, const float* __restrict__ sbf0,
        const float* __restrict__ b_p4)
{
    extern __shared__ char sm[];
    u32 smu = smem_u32(sm);
    int tid = threadIdx.x, w = tid >> 5, lane = tid & 31;
    int mrow = (w & 3) * 32, wn = w >> 2;
    int r0 = blockIdx.x * 128;
    float* P = (float*)(sm + P_OFF);
    float acc[32];

    stageW_async(smu, WE_P4, 128);
    stage_split(sm, x1 + (size_t)r0 * 128, 128, 128, 64);
    CP_WAIT(); __syncthreads();
    za<32>(acc); wgemm<4>(smu, 8, acc, mrow, wn * 32, lane);
    __syncthreads();
    stageW_async(smu, WE_SBFC, 48);
    epi<4>(acc, mrow, wn * 32, lane, [&](int rr, int col, float* cc) {
        float2 bb = *(const float2*)(b_p4 + col);
        *(float2*)(P + rr * PSTR + col) = make_float2(siluf(cc[0] + bb.x), siluf(cc[1] + bb.y));
    });
    stage_split(sm, sbf0 + (size_t)r0 * 42, 42, 42, 24);
    CP_WAIT(); __syncthreads();
    za<32>(acc); wgemm<4>(smu, 3, acc, mrow, wn * 32, lane);
    __syncthreads();
    stageW_async(smu, WE_DOWN, 128);
    epi<4>(acc, mrow, wn * 32, lane, [&](int rr, int col, float* cc) {
        float2 pv = *(float2*)(P + rr * PSTR + col);
        splitA(sm, rr, col, cc[0] * pv.x, cc[1] * pv.y);
    });
    CP_WAIT(); __syncthreads();
    za<16>(acc); wgemm<2>(smu, 8, acc, mrow, wn * 16, lane);
    epi<2>(acc, mrow, wn * 16, lane, [&](int rr, int col, float* cc) {
        *(float2*)(g_t + (size_t)(r0 + rr) * 64 + col) = make_float2(siluf(cc[0]), siluf(cc[1]));
    });
}

// ---------------- Kernel B: full tail ----------------
extern "C" __global__ void __launch_bounds__(NTHR, 1)
kernelB(const float* __restrict__ ta, const float* __restrict__ sbf0,
        const int* __restrict__ p_idx, const float* __restrict__ x1,
        const float* __restrict__ b_p2,
        const float* __restrict__ rb_b1, const float* __restrict__ rb_b2,
        const float* __restrict__ b_lin,
        const float* __restrict__ ra_b1, const float* __restrict__ ra_b2,
        float* __restrict__ out)
{
    extern __shared__ char sm[];
    u32 smu = smem_u32(sm);
    int tid = threadIdx.x, w = tid >> 5, lane = tid & 31;
    int mrow = (w & 3) * 32, wn = w >> 2;
    int r0 = blockIdx.x * 128;
    float* P = (float*)(sm + P_OFF);
    float acc[32];
    int nc128 = wn * 32, nc64 = wn * 16;

    // G1: x_p2 = silu(x1@Wp2 + b) -> P
    stageW_async(smu, WE_P2, 128);
    stage_split(sm, x1 + (size_t)r0 * 128, 128, 128, 64);
    CP_WAIT(); __syncthreads();
    za<32>(acc); wgemm<4>(smu, 8, acc, mrow, nc128, lane);
    __syncthreads();
    stageW_async(smu, WE_TC0, 128);
    epi<4>(acc, mrow, nc128, lane, [&](int rr, int col, float* cc) {
        float2 bb = *(const float2*)(b_p2 + col);
        *(float2*)(P + rr * PSTR + col) = make_float2(siluf(cc[0] + bb.x), siluf(cc[1] + bb.y));
    });
    stage_split(sm, ta + (size_t)r0 * 294 + 0, 294, 128, 64);
    CP_WAIT(); __syncthreads();

    // G2: ta_p = ta@WtC (3 chunks, reg-accumulated)
    za<16>(acc);
    wgemm<2>(smu, 8, acc, mrow, nc64, lane);
    __syncthreads();
    stageW_async(smu, WE_TC1, 128);
    stage_split(sm, ta + (size_t)r0 * 294 + 128, 294, 128, 64);
    CP_WAIT(); __syncthreads();
    wgemm<2>(smu, 8, acc, mrow, nc64, lane);
    __syncthreads();
    stageW_async(smu, WE_TC2, 48);
    stage_split(sm, ta + (size_t)r0 * 294 + 256, 294, 38, 24);
    CP_WAIT(); __syncthreads();
    wgemm<2>(smu, 3, acc, mrow, nc64, lane);
    __syncthreads();
    stageW_async(smu, WE_UP, 64);
    epi<2>(acc, mrow, nc64, lane, [&](int rr, int col, float* cc) {
        int idx = p_idx[r0 + rr];
        float2 tv = *(const float2*)(g_t + (size_t)idx * 64 + col);
        splitA(sm, rr, col, cc[0] * tv.x, cc[1] * tv.y);
    });
    CP_WAIT(); __syncthreads();

    // G3: p1 = silu(g@Wup) + x_p2 -> P, A
    za<32>(acc); wgemm<4>(smu, 4, acc, mrow, nc128, lane);
    __syncthreads();
    stageW_async(smu, WE_RB1, 128);
    epi<4>(acc, mrow, nc128, lane, [&](int rr, int col, float* cc) {
        float* pp = P + rr * PSTR + col;
        float v0 = siluf(cc[0]) + pp[0];
        float v1 = siluf(cc[1]) + pp[1];
        pp[0] = v0; pp[1] = v1;
        splitA(sm, rr, col, v0, v1);
    });
    CP_WAIT(); __syncthreads();

    // G4..G9: RB1, RB2, LIN, RA1A, RA2A, RA1B
    const int entN[6] = { WE_RB2, WE_LIN, WE_RA1A, WE_RA2A, WE_RA1B, WE_RA2B };
    const float* bs1[6] = { rb_b1, rb_b2, b_lin, ra_b1, ra_b2, ra_b1 + 128 };
    #pragma unroll 1
    for (int s = 0; s < 6; s++) {
        za<32>(acc); wgemm<4>(smu, 8, acc, mrow, nc128, lane);
        __syncthreads();
        stageW_async(smu, entN[s], 128);
        const float* bb_ = bs1[s];
        if (s == 0 || s == 3 || s == 5) {           // first half of res block: A = silu(v+b)
            epi<4>(acc, mrow, nc128, lane, [&](int rr, int col, float* cc) {
                float2 bb = *(const float2*)(bb_ + col);
                splitA(sm, rr, col, siluf(cc[0] + bb.x), siluf(cc[1] + bb.y));
            });
        } else if (s == 1 || s == 4) {              // second half: P += silu(v+b); A = P
            epi<4>(acc, mrow, nc128, lane, [&](int rr, int col, float* cc) {
                float2 bb = *(const float2*)(bb_ + col);
                float* pp = P + rr * PSTR + col;
                float v0 = pp[0] + siluf(cc[0] + bb.x);
                float v1 = pp[1] + siluf(cc[1] + bb.y);
                pp[0] = v0; pp[1] = v1;
                splitA(sm, rr, col, v0, v1);
            });
        } else {                                    // lin: P = silu(v+b) + x1; A = P
            epi<4>(acc, mrow, nc128, lane, [&](int rr, int col, float* cc) {
                float2 bb = *(const float2*)(bb_ + col);
                float2 xv = *(const float2*)(x1 + (size_t)(r0 + rr) * 128 + col);
                float* pp = P + rr * PSTR + col;
                float v0 = siluf(cc[0] + bb.x) + xv.x;
                float v1 = siluf(cc[1] + bb.y) + xv.y;
                pp[0] = v0; pp[1] = v1;
                splitA(sm, rr, col, v0, v1);
            });
        }
        CP_WAIT(); __syncthreads();
    }

    // G10: RA2B — p1 final: P += silu(v+b); write out p1
    za<32>(acc); wgemm<4>(smu, 8, acc, mrow, nc128, lane);
    __syncthreads();
    stageW_async(smu, WE_SBF, 48);
    epi<4>(acc, mrow, nc128, lane, [&](int rr, int col, float* cc) {
        float2 bb = *(const float2*)(ra_b2 + 128 + col);
        float* pp = P + rr * PSTR + col;
        float v0 = pp[0] + siluf(cc[0] + bb.x);
        float v1 = pp[1] + siluf(cc[1] + bb.y);
        pp[0] = v0; pp[1] = v1;
        *(float2*)(out + (size_t)(r0 + rr) * 128 + col) = make_float2(v0, v1);
    });
    stage_split(sm, sbf0 + (size_t)r0 * 42, 42, 42, 24);
    CP_WAIT(); __syncthreads();

    // G11: p2 = (sbf0@Wsbf) * p1
    za<32>(acc); wgemm<4>(smu, 3, acc, mrow, nc128, lane);
    float* out2 = out + (size_t)E_EDGES * 128;
    epi<4>(acc, mrow, nc128, lane, [&](int rr, int col, float* cc) {
        float* pp = P + rr * PSTR + col;
        *(float2*)(out2 + (size_t)(r0 + rr) * 128 + col) = make_float2(cc[0] * pp[0], cc[1] * pp[1]);
    });
}

// ---------------- launch ----------------
extern "C" void kernel_launch(void* const* d_in, const int* in_sizes, int n_in,
                              void* d_out, int out_size)
{
    const float* x1     = (const float*)d_in[0];
    const float* sbf0   = (const float*)d_in[1];
    const float* ta     = (const float*)d_in[2];
    const int*   p_idx  = (const int*)  d_in[3];
    const float* w_p2   = (const float*)d_in[4];
    const float* b_p2   = (const float*)d_in[5];
    const float* w_p4   = (const float*)d_in[6];
    const float* b_p4   = (const float*)d_in[7];
    const float* w_sbf1 = (const float*)d_in[8];
    const float* w_sbf2 = (const float*)d_in[9];
    const float* w_t1   = (const float*)d_in[10];
    const float* w_t2   = (const float*)d_in[11];
    const float* w_down = (const float*)d_in[12];
    const float* w_up   = (const float*)d_in[13];
    const float* rb_w1  = (const float*)d_in[14];
    const float* rb_b1  = (const float*)d_in[15];
    const float* rb_w2  = (const float*)d_in[16];
    const float* rb_b2  = (const float*)d_in[17];
    const float* w_lin  = (const float*)d_in[18];
    const float* b_lin  = (const float*)d_in[19];
    const float* ra_w1  = (const float*)d_in[20];
    const float* ra_b1  = (const float*)d_in[21];
    const float* ra_w2  = (const float*)d_in[22];
    const float* ra_b2  = (const float*)d_in[23];
    const float* w_sbf  = (const float*)d_in[24];
    float* out = (float*)d_out;

    cudaFuncSetAttribute(kernelA, cudaFuncAttributeMaxDynamicSharedMemorySize, SMEM_TOTAL);
    cudaFuncSetAttribute(kernelB, cudaFuncAttributeMaxDynamicSharedMemorySize, SMEM_TOTAL);

    setup_kernel<<<128, 256>>>(w_p2, w_p4, w_sbf1, w_sbf2, w_t1, w_t2, w_down, w_up,
                               rb_w1, rb_w2, w_lin, ra_w1, ra_w2, w_sbf);
    kernelA<<<E_EDGES / 128, NTHR, SMEM_TOTAL>>>(x1, sbf0, b_p4);
    kernelB<<<E_EDGES / 128, NTHR, SMEM_TOTAL>>>(ta, sbf0, p_idx, x1, b_p2,
                                                 rb_b1, rb_b2, b_lin, ra_b1, ra_b2, out);
}

// round 15
// speedup vs baseline: 3.0901x; 1.1631x over previous
#include <cuda_runtime.h>
#include <cuda_bf16.h>

typedef unsigned int u32;

#define E_EDGES 400000
#define NTHR 256
#define ASTR 136
#define WSTR 136

// smem byte offsets (per 64-row CTA)
#define A_HI 0
#define A_LO 17408
#define W_HI 34816
#define W_LO 69632
#define SMEM_TOTAL 104448

enum { WE_P2=0, WE_P4, WE_RB1, WE_RB2, WE_LIN, WE_RA1A, WE_RA2A, WE_RA1B, WE_RA2B,
       WE_SBFC, WE_SBF, WE_DOWN, WE_UP, WE_TC0, WE_TC1, WE_TC2, WE_COUNT };

// each entry is the exact smem W image: hi at +0 (K rows x WSTR stride), lo at +17408 elems
#define WENT 34816
__device__ __align__(16) __nv_bfloat16 g_wb[WE_COUNT * WENT];
__device__ float g_t[(size_t)E_EDGES * 64];

__device__ __forceinline__ u32 smem_u32(const void* p) {
    u32 a; asm("{ .reg .u64 t; cvta.to.shared.u64 t, %1; cvt.u32.u64 %0, t; }" : "=r"(a) : "l"(p));
    return a;
}
__device__ __forceinline__ float siluf(float x) { return __fdividef(x, 1.0f + __expf(-x)); }

__device__ __forceinline__ void ldmA(u32 addr, u32 &r0, u32 &r1, u32 &r2, u32 &r3) {
    asm volatile("ldmatrix.sync.aligned.m8n8.x4.shared.b16 {%0,%1,%2,%3}, [%4];"
                 : "=r"(r0), "=r"(r1), "=r"(r2), "=r"(r3) : "r"(addr));
}
__device__ __forceinline__ void ldmB4f(u32 addr, u32 &r0, u32 &r1, u32 &r2, u32 &r3) {
    asm volatile("ldmatrix.sync.aligned.m8n8.x4.trans.shared.b16 {%0,%1,%2,%3}, [%4];"
                 : "=r"(r0), "=r"(r1), "=r"(r2), "=r"(r3) : "r"(addr));
}
__device__ __forceinline__ void mma16816(float* c, u32 a0, u32 a1, u32 a2, u32 a3, u32 b0, u32 b1) {
    asm volatile("mma.sync.aligned.m16n8k16.row.col.f32.bf16.bf16.f32 "
                 "{%0,%1,%2,%3},{%4,%5,%6,%7},{%8,%9},{%0,%1,%2,%3};"
                 : "+f"(c[0]), "+f"(c[1]), "+f"(c[2]), "+f"(c[3])
                 : "r"(a0), "r"(a1), "r"(a2), "r"(a3), "r"(b0), "r"(b1));
}
template<int N>
__device__ __forceinline__ void za(float* a) {
    #pragma unroll
    for (int i = 0; i < N; i++) a[i] = 0.f;
}
__device__ __forceinline__ void cpasync16(u32 sa, const void* ga) {
    asm volatile("cp.async.cg.shared.global [%0], [%1], 16;" :: "r"(sa), "l"(ga) : "memory");
}
#define CP_COMMIT() asm volatile("cp.async.commit_group;" ::: "memory")
#define CP_WAIT()   asm volatile("cp.async.wait_group 0;" ::: "memory")

// ---------------- setup: fold, split hi/lo, store smem-image layout ----------------
__global__ void setup_kernel(
    const float* __restrict__ w_p2, const float* __restrict__ w_p4,
    const float* __restrict__ w_sbf1, const float* __restrict__ w_sbf2,
    const float* __restrict__ w_t1, const float* __restrict__ w_t2,
    const float* __restrict__ w_down, const float* __restrict__ w_up,
    const float* __restrict__ rb_w1, const float* __restrict__ rb_w2,
    const float* __restrict__ w_lin,
    const float* __restrict__ ra_w1, const float* __restrict__ ra_w2,
    const float* __restrict__ w_sbf)
{
    int tid = blockIdx.x * blockDim.x + threadIdx.x;
    int nt = gridDim.x * blockDim.x;
    const float* Wsrc[9] = { w_p2, w_p4, rb_w1, rb_w2, w_lin, ra_w1, ra_w2, ra_w1 + 16384, ra_w2 + 16384 };
    const int Went[9] = { WE_P2, WE_P4, WE_RB1, WE_RB2, WE_LIN, WE_RA1A, WE_RA2A, WE_RA1B, WE_RA2B };
    for (int e = 0; e < 9; e++) {
        __nv_bfloat16* dst = g_wb + Went[e] * WENT;
        for (int i = tid; i < 16384; i += nt) {   // i = k*128 + n
            int k = i >> 7, n = i & 127;
            float v = Wsrc[e][n * 128 + k];
            __nv_bfloat16 h = __float2bfloat16(v);
            int o = k * WSTR + n;
            dst[o] = h; dst[17408 + o] = __float2bfloat16(v - __bfloat162float(h));
        }
    }
    {   // SBFC: K=48(42 valid), N=128 folded
        __nv_bfloat16* dst = g_wb + WE_SBFC * WENT;
        for (int i = tid; i < 48 * 128; i += nt) {
            int k = i >> 7, n = i & 127; float v = 0.f;
            if (k < 42) {
                for (int b = 0; b < 8; b++) v += w_sbf2[n * 8 + b] * w_sbf1[b * 42 + k];
            }
            __nv_bfloat16 h = __float2bfloat16(v);
            int o = k * WSTR + n;
            dst[o] = h; dst[17408 + o] = __float2bfloat16(v - __bfloat162float(h));
        }
    }
    {   // SBF: K=48, N=128
        __nv_bfloat16* dst = g_wb + WE_SBF * WENT;
        for (int i = tid; i < 48 * 128; i += nt) {
            int k = i >> 7, n = i & 127;
            float v = (k < 42) ? w_sbf[n * 42 + k] : 0.f;
            __nv_bfloat16 h = __float2bfloat16(v);
            int o = k * WSTR + n;
            dst[o] = h; dst[17408 + o] = __float2bfloat16(v - __bfloat162float(h));
        }
    }
    {   // DOWN: K=128, N=64
        __nv_bfloat16* dst = g_wb + WE_DOWN * WENT;
        for (int i = tid; i < 128 * 64; i += nt) {
            int k = i >> 6, n = i & 63;
            float v = w_down[n * 128 + k];
            __nv_bfloat16 h = __float2bfloat16(v);
            int o = k * WSTR + n;
            dst[o] = h; dst[17408 + o] = __float2bfloat16(v - __bfloat162float(h));
        }
    }
    {   // UP: K=64, N=128
        __nv_bfloat16* dst = g_wb + WE_UP * WENT;
        for (int i = tid; i < 64 * 128; i += nt) {
            int k = i >> 7, n = i & 127;
            float v = w_up[n * 64 + k];
            __nv_bfloat16 h = __float2bfloat16(v);
            int o = k * WSTR + n;
            dst[o] = h; dst[17408 + o] = __float2bfloat16(v - __bfloat162float(h));
        }
    }
    for (int c = 0; c < 3; c++) {   // TC: N=64, K 128/128/48, folded
        int kp = (c < 2) ? 128 : 48;
        __nv_bfloat16* dst = g_wb + (WE_TC0 + c) * WENT;
        for (int i = tid; i < kp * 64; i += nt) {
            int k = i >> 6, n = i & 63, kg = c * 128 + k;
            float v = 0.f;
            if (kg < 294) {
                for (int b = 0; b < 8; b++) v += w_t2[n * 8 + b] * w_t1[b * 294 + kg];
            }
            __nv_bfloat16 h = __float2bfloat16(v);
            int o = k * WSTR + n;
            dst[o] = h; dst[17408 + o] = __float2bfloat16(v - __bfloat162float(h));
        }
    }
}

// ---------------- staging ----------------
__device__ __forceinline__ void stageW_async(u32 smu, int entry, int K) {
    const char* src = (const char*)(g_wb + entry * WENT);
    int nbytes = K * (WSTR * 2);
    for (int i = threadIdx.x * 16; i < nbytes; i += NTHR * 16) {
        cpasync16(smu + W_HI + i, src + i);
        cpasync16(smu + W_LO + i, src + 34816 + i);
    }
    CP_COMMIT();
}
__device__ __forceinline__ void splitA(char* sm, int rr, int col, float a, float b) {
    __nv_bfloat162 h = __floats2bfloat162_rn(a, b);
    __nv_bfloat162 lo = __floats2bfloat162_rn(a - __bfloat162float(h.x), b - __bfloat162float(h.y));
    int off = (rr * ASTR + col) * 2;
    *(__nv_bfloat162*)(sm + A_HI + off) = h;
    *(__nv_bfloat162*)(sm + A_LO + off) = lo;
}
// 64-row tile
__device__ __forceinline__ void stage_split(char* sm, const float* __restrict__ src,
                                            int rstride, int kvalid, int npairs) {
    for (int i = threadIdx.x; i < 64 * npairs; i += NTHR) {
        int rr = i / npairs, jp = i - rr * npairs;
        float2 xv = (2 * jp < kvalid) ? *(const float2*)(src + (size_t)rr * rstride + 2 * jp)
                                      : make_float2(0.f, 0.f);
        splitA(sm, rr, 2 * jp, xv.x, xv.y);
    }
}

// ---------------- warp GEMM: 3-pass bf16 split; 8 warps (2M x 4N), 32x32 / 32x16 each ----------------
template<int NB>
__device__ __forceinline__ void wgemm(u32 smu, int nk, float* acc, int mrow, int ncol, int lane) {
    u32 aoff = (u32)((mrow + (lane & 15)) * ASTR + ((lane >> 4) << 3)) * 2;
    u32 boff = (u32)((lane & 15) * WSTR + ncol + ((lane >> 4) << 3)) * 2;
    #pragma unroll
    for (int p = 0; p < 3; p++) {
        u32 aBase = smu + (p == 2 ? A_LO : A_HI) + aoff;
        u32 bBase = smu + (p == 1 ? W_LO : W_HI) + boff;
        for (int kc = 0; kc < nk; kc++) {
            u32 a0, a1, a2, a3, a4, a5, a6, a7;
            u32 aA = aBase + kc * 32;
            ldmA(aA, a0, a1, a2, a3);
            ldmA(aA + 16 * ASTR * 2, a4, a5, a6, a7);
            u32 bA = bBase + kc * 16 * WSTR * 2;
            #pragma unroll
            for (int nb2 = 0; nb2 < NB / 2; nb2++) {
                u32 b0, b1, b2, b3;
                ldmB4f(bA + nb2 * 32, b0, b1, b2, b3);
                mma16816(acc + nb2 * 8,                a0, a1, a2, a3, b0, b1);
                mma16816(acc + nb2 * 8 + 4,            a0, a1, a2, a3, b2, b3);
                mma16816(acc + (NB + nb2 * 2) * 4,     a4, a5, a6, a7, b0, b1);
                mma16816(acc + (NB + nb2 * 2 + 1) * 4, a4, a5, a6, a7, b2, b3);
            }
        }
    }
}

// epilogue iteration: lambda gets (rr, col, cc, idx) where idx indexes the acc/P register arrays
template<int NB, typename F>
__device__ __forceinline__ void epi(float* acc, int mrow, int ncol, int lane, F f) {
    #pragma unroll
    for (int mt = 0; mt < 2; mt++)
    #pragma unroll
    for (int nb = 0; nb < NB; nb++) {
        int col = ncol + nb * 8 + (lane & 3) * 2;
        #pragma unroll
        for (int ri = 0; ri < 2; ri++) {
            int rr = mrow + mt * 16 + (lane >> 2) + ri * 8;
            int idx = (mt * NB + nb) * 4 + ri * 2;
            f(rr, col, acc + idx, idx);
        }
    }
}

// ---------------- Kernel A: g_t = silu((silu(x1@Wp4+b)*sbf)@Wdown), 64-row tiles ----------------
extern "C" __global__ void __launch_bounds__(NTHR, 2)
kernelA(const float* __restrict__ x1, const float* __restrict__ sbf0,
        const float* __restrict__ b_p4)
{
    extern __shared__ char sm[];
    u32 smu = smem_u32(sm);
    int tid = threadIdx.x, w = tid >> 5, lane = tid & 31;
    int mrow = (w & 1) * 32, wn = w >> 1;
    int r0 = blockIdx.x * 64;
    float acc[32], P[32];

    stageW_async(smu, WE_P4, 128);
    stage_split(sm, x1 + (size_t)r0 * 128, 128, 128, 64);
    CP_WAIT(); __syncthreads();
    za<32>(acc); wgemm<4>(smu, 8, acc, mrow, wn * 32, lane);
    __syncthreads();
    stageW_async(smu, WE_SBFC, 48);
    epi<4>(acc, mrow, wn * 32, lane, [&](int rr, int col, float* cc, int idx) {
        float2 bb = *(const float2*)(b_p4 + col);
        P[idx] = siluf(cc[0] + bb.x); P[idx + 1] = siluf(cc[1] + bb.y);
    });
    stage_split(sm, sbf0 + (size_t)r0 * 42, 42, 42, 24);
    CP_WAIT(); __syncthreads();
    za<32>(acc); wgemm<4>(smu, 3, acc, mrow, wn * 32, lane);
    __syncthreads();
    stageW_async(smu, WE_DOWN, 128);
    epi<4>(acc, mrow, wn * 32, lane, [&](int rr, int col, float* cc, int idx) {
        splitA(sm, rr, col, cc[0] * P[idx], cc[1] * P[idx + 1]);
    });
    CP_WAIT(); __syncthreads();
    za<16>(acc); wgemm<2>(smu, 8, acc, mrow, wn * 16, lane);
    epi<2>(acc, mrow, wn * 16, lane, [&](int rr, int col, float* cc, int idx) {
        *(float2*)(g_t + (size_t)(r0 + rr) * 64 + col) = make_float2(siluf(cc[0]), siluf(cc[1]));
    });
}

// ---------------- Kernel B: full tail, 64-row tiles, P in registers ----------------
extern "C" __global__ void __launch_bounds__(NTHR, 2)
kernelB(const float* __restrict__ ta, const float* __restrict__ sbf0,
        const int* __restrict__ p_idx, const float* __restrict__ x1,
        const float* __restrict__ b_p2,
        const float* __restrict__ rb_b1, const float* __restrict__ rb_b2,
        const float* __restrict__ b_lin,
        const float* __restrict__ ra_b1, const float* __restrict__ ra_b2,
        float* __restrict__ out)
{
    extern __shared__ char sm[];
    u32 smu = smem_u32(sm);
    int tid = threadIdx.x, w = tid >> 5, lane = tid & 31;
    int mrow = (w & 1) * 32, wn = w >> 1;
    int r0 = blockIdx.x * 64;
    float acc[32], P[32];
    int nc128 = wn * 32, nc64 = wn * 16;

    // G1: x_p2 = silu(x1@Wp2 + b) -> P regs
    stageW_async(smu, WE_P2, 128);
    stage_split(sm, x1 + (size_t)r0 * 128, 128, 128, 64);
    CP_WAIT(); __syncthreads();
    za<32>(acc); wgemm<4>(smu, 8, acc, mrow, nc128, lane);
    __syncthreads();
    stageW_async(smu, WE_TC0, 128);
    epi<4>(acc, mrow, nc128, lane, [&](int rr, int col, float* cc, int idx) {
        float2 bb = *(const float2*)(b_p2 + col);
        P[idx] = siluf(cc[0] + bb.x); P[idx + 1] = siluf(cc[1] + bb.y);
    });
    stage_split(sm, ta + (size_t)r0 * 294 + 0, 294, 128, 64);
    CP_WAIT(); __syncthreads();

    // G2: ta_p = ta@WtC (3 chunks, reg-accumulated)
    za<16>(acc);
    wgemm<2>(smu, 8, acc, mrow, nc64, lane);
    __syncthreads();
    stageW_async(smu, WE_TC1, 128);
    stage_split(sm, ta + (size_t)r0 * 294 + 128, 294, 128, 64);
    CP_WAIT(); __syncthreads();
    wgemm<2>(smu, 8, acc, mrow, nc64, lane);
    __syncthreads();
    stageW_async(smu, WE_TC2, 48);
    stage_split(sm, ta + (size_t)r0 * 294 + 256, 294, 38, 24);
    CP_WAIT(); __syncthreads();
    wgemm<2>(smu, 3, acc, mrow, nc64, lane);
    __syncthreads();
    stageW_async(smu, WE_UP, 64);
    epi<2>(acc, mrow, nc64, lane, [&](int rr, int col, float* cc, int idx) {
        int idxg = p_idx[r0 + rr];
        float2 tv = *(const float2*)(g_t + (size_t)idxg * 64 + col);
        splitA(sm, rr, col, cc[0] * tv.x, cc[1] * tv.y);
    });
    CP_WAIT(); __syncthreads();

    // G3: p1 = silu(g@Wup) + x_p2 -> P regs, A
    za<32>(acc); wgemm<4>(smu, 4, acc, mrow, nc128, lane);
    __syncthreads();
    stageW_async(smu, WE_RB1, 128);
    epi<4>(acc, mrow, nc128, lane, [&](int rr, int col, float* cc, int idx) {
        float v0 = siluf(cc[0]) + P[idx];
        float v1 = siluf(cc[1]) + P[idx + 1];
        P[idx] = v0; P[idx + 1] = v1;
        splitA(sm, rr, col, v0, v1);
    });
    CP_WAIT(); __syncthreads();

    // G4..G9: RB1, RB2, LIN, RA1A, RA2A, RA1B (prefetch next; bias matches current)
    const int entN[6] = { WE_RB2, WE_LIN, WE_RA1A, WE_RA2A, WE_RA1B, WE_RA2B };
    const float* bs1[6] = { rb_b1, rb_b2, b_lin, ra_b1, ra_b2, ra_b1 + 128 };
    #pragma unroll 1
    for (int s = 0; s < 6; s++) {
        za<32>(acc); wgemm<4>(smu, 8, acc, mrow, nc128, lane);
        __syncthreads();
        stageW_async(smu, entN[s], 128);
        const float* bb_ = bs1[s];
        if (s == 0 || s == 3 || s == 5) {           // first half of res block: A = silu(v+b)
            epi<4>(acc, mrow, nc128, lane, [&](int rr, int col, float* cc, int idx) {
                float2 bb = *(const float2*)(bb_ + col);
                splitA(sm, rr, col, siluf(cc[0] + bb.x), siluf(cc[1] + bb.y));
            });
        } else if (s == 1 || s == 4) {              // second half: P += silu(v+b); A = P
            epi<4>(acc, mrow, nc128, lane, [&](int rr, int col, float* cc, int idx) {
                float2 bb = *(const float2*)(bb_ + col);
                float v0 = P[idx] + siluf(cc[0] + bb.x);
                float v1 = P[idx + 1] + siluf(cc[1] + bb.y);
                P[idx] = v0; P[idx + 1] = v1;
                splitA(sm, rr, col, v0, v1);
            });
        } else {                                    // lin: P = silu(v+b) + x1; A = P
            epi<4>(acc, mrow, nc128, lane, [&](int rr, int col, float* cc, int idx) {
                float2 bb = *(const float2*)(bb_ + col);
                float2 xv = *(const float2*)(x1 + (size_t)(r0 + rr) * 128 + col);
                float v0 = siluf(cc[0] + bb.x) + xv.x;
                float v1 = siluf(cc[1] + bb.y) + xv.y;
                P[idx] = v0; P[idx + 1] = v1;
                splitA(sm, rr, col, v0, v1);
            });
        }
        CP_WAIT(); __syncthreads();
    }

    // G10: RA2B — p1 final: P += silu(v+b); write out p1
    za<32>(acc); wgemm<4>(smu, 8, acc, mrow, nc128, lane);
    __syncthreads();
    stageW_async(smu, WE_SBF, 48);
    epi<4>(acc, mrow, nc128, lane, [&](int rr, int col, float* cc, int idx) {
        float2 bb = *(const float2*)(ra_b2 + 128 + col);
        float v0 = P[idx] + siluf(cc[0] + bb.x);
        float v1 = P[idx + 1] + siluf(cc[1] + bb.y);
        P[idx] = v0; P[idx + 1] = v1;
        *(float2*)(out + (size_t)(r0 + rr) * 128 + col) = make_float2(v0, v1);
    });
    stage_split(sm, sbf0 + (size_t)r0 * 42, 42, 42, 24);
    CP_WAIT(); __syncthreads();

    // G11: p2 = (sbf0@Wsbf) * p1
    za<32>(acc); wgemm<4>(smu, 3, acc, mrow, nc128, lane);
    float* out2 = out + (size_t)E_EDGES * 128;
    epi<4>(acc, mrow, nc128, lane, [&](int rr, int col, float* cc, int idx) {
        *(float2*)(out2 + (size_t)(r0 + rr) * 128 + col) = make_float2(cc[0] * P[idx], cc[1] * P[idx + 1]);
    });
}

// ---------------- launch ----------------
extern "C" void kernel_launch(void* const* d_in, const int* in_sizes, int n_in,
                              void* d_out, int out_size)
{
    const float* x1     = (const float*)d_in[0];
    const float* sbf0   = (const float*)d_in[1];
    const float* ta     = (const float*)d_in[2];
    const int*   p_idx  = (const int*)  d_in[3];
    const float* w_p2   = (const float*)d_in[4];
    const float* b_p2   = (const float*)d_in[5];
    const float* w_p4   = (const float*)d_in[6];
    const float* b_p4   = (const float*)d_in[7];
    const float* w_sbf1 = (const float*)d_in[8];
    const float* w_sbf2 = (const float*)d_in[9];
    const float* w_t1   = (const float*)d_in[10];
    const float* w_t2   = (const float*)d_in[11];
    const float* w_down = (const float*)d_in[12];
    const float* w_up   = (const float*)d_in[13];
    const float* rb_w1  = (const float*)d_in[14];
    const float* rb_b1  = (const float*)d_in[15];
    const float* rb_w2  = (const float*)d_in[16];
    const float* rb_b2  = (const float*)d_in[17];
    const float* w_lin  = (const float*)d_in[18];
    const float* b_lin  = (const float*)d_in[19];
    const float* ra_w1  = (const float*)d_in[20];
    const float* ra_b1  = (const float*)d_in[21];
    const float* ra_w2  = (const float*)d_in[22];
    const float* ra_b2  = (const float*)d_in[23];
    const float* w_sbf  = (const float*)d_in[24];
    float* out = (float*)d_out;

    cudaFuncSetAttribute(kernelA, cudaFuncAttributeMaxDynamicSharedMemorySize, SMEM_TOTAL);
    cudaFuncSetAttribute(kernelB, cudaFuncAttributeMaxDynamicSharedMemorySize, SMEM_TOTAL);

    setup_kernel<<<128, 256>>>(w_p2, w_p4, w_sbf1, w_sbf2, w_t1, w_t2, w_down, w_up,
                               rb_w1, rb_w2, w_lin, ra_w1, ra_w2, w_sbf);
    kernelA<<<E_EDGES / 64, NTHR, SMEM_TOTAL>>>(x1, sbf0, b_p4);
    kernelB<<<E_EDGES / 64, NTHR, SMEM_TOTAL>>>(ta, sbf0, p_idx, x1, b_p2,
                                                rb_b1, rb_b2, b_lin, ra_b1, ra_b2, out);
}

// round 16
// speedup vs baseline: 4.2743x; 1.3832x over previous
#include <cuda_runtime.h>
#include <cuda_fp16.h>

typedef unsigned int u32;

#define E_EDGES 400000
#define NTHR 256
#define ASTR 136
#define WSTR 136

// smem byte offsets (per 64-row CTA)
#define A_HI 0
#define A_LO 17408
#define W_OFF 34816
#define SMEM_TOTAL 69632

enum { WE_P2=0, WE_P4, WE_RB1, WE_RB2, WE_LIN, WE_RA1A, WE_RA2A, WE_RA1B, WE_RA2B,
       WE_SBFC, WE_SBF, WE_DOWN, WE_UP, WE_TC0, WE_TC1, WE_TC2, WE_COUNT };

// each entry is the exact smem W image: single fp16, K rows x WSTR stride
#define WENT 17408
__device__ __align__(16) __half g_wb[WE_COUNT * WENT];
__device__ float g_t[(size_t)E_EDGES * 64];

__device__ __forceinline__ u32 smem_u32(const void* p) {
    u32 a; asm("{ .reg .u64 t; cvta.to.shared.u64 t, %1; cvt.u32.u64 %0, t; }" : "=r"(a) : "l"(p));
    return a;
}
__device__ __forceinline__ float siluf(float x) { return __fdividef(x, 1.0f + __expf(-x)); }

__device__ __forceinline__ void ldmA(u32 addr, u32 &r0, u32 &r1, u32 &r2, u32 &r3) {
    asm volatile("ldmatrix.sync.aligned.m8n8.x4.shared.b16 {%0,%1,%2,%3}, [%4];"
                 : "=r"(r0), "=r"(r1), "=r"(r2), "=r"(r3) : "r"(addr));
}
__device__ __forceinline__ void ldmB4f(u32 addr, u32 &r0, u32 &r1, u32 &r2, u32 &r3) {
    asm volatile("ldmatrix.sync.aligned.m8n8.x4.trans.shared.b16 {%0,%1,%2,%3}, [%4];"
                 : "=r"(r0), "=r"(r1), "=r"(r2), "=r"(r3) : "r"(addr));
}
__device__ __forceinline__ void mma16816(float* c, u32 a0, u32 a1, u32 a2, u32 a3, u32 b0, u32 b1) {
    asm volatile("mma.sync.aligned.m16n8k16.row.col.f32.f16.f16.f32 "
                 "{%0,%1,%2,%3},{%4,%5,%6,%7},{%8,%9},{%0,%1,%2,%3};"
                 : "+f"(c[0]), "+f"(c[1]), "+f"(c[2]), "+f"(c[3])
                 : "r"(a0), "r"(a1), "r"(a2), "r"(a3), "r"(b0), "r"(b1));
}
template<int N>
__device__ __forceinline__ void za(float* a) {
    #pragma unroll
    for (int i = 0; i < N; i++) a[i] = 0.f;
}
__device__ __forceinline__ void cpasync16(u32 sa, const void* ga) {
    asm volatile("cp.async.cg.shared.global [%0], [%1], 16;" :: "r"(sa), "l"(ga) : "memory");
}
#define CP_COMMIT() asm volatile("cp.async.commit_group;" ::: "memory")
#define CP_WAIT()   asm volatile("cp.async.wait_group 0;" ::: "memory")

// ---------------- setup: fold, store fp16 smem-image layout ----------------
__global__ void setup_kernel(
    const float* __restrict__ w_p2, const float* __restrict__ w_p4,
    const float* __restrict__ w_sbf1, const float* __restrict__ w_sbf2,
    const float* __restrict__ w_t1, const float* __restrict__ w_t2,
    const float* __restrict__ w_down, const float* __restrict__ w_up,
    const float* __restrict__ rb_w1, const float* __restrict__ rb_w2,
    const float* __restrict__ w_lin,
    const float* __restrict__ ra_w1, const float* __restrict__ ra_w2,
    const float* __restrict__ w_sbf)
{
    int tid = blockIdx.x * blockDim.x + threadIdx.x;
    int nt = gridDim.x * blockDim.x;
    const float* Wsrc[9] = { w_p2, w_p4, rb_w1, rb_w2, w_lin, ra_w1, ra_w2, ra_w1 + 16384, ra_w2 + 16384 };
    const int Went[9] = { WE_P2, WE_P4, WE_RB1, WE_RB2, WE_LIN, WE_RA1A, WE_RA2A, WE_RA1B, WE_RA2B };
    for (int e = 0; e < 9; e++) {
        __half* dst = g_wb + Went[e] * WENT;
        for (int i = tid; i < 16384; i += nt) {   // i = k*128 + n
            int k = i >> 7, n = i & 127;
            dst[k * WSTR + n] = __float2half_rn(Wsrc[e][n * 128 + k]);
        }
    }
    {   // SBFC: K=48(42 valid), N=128 folded
        __half* dst = g_wb + WE_SBFC * WENT;
        for (int i = tid; i < 48 * 128; i += nt) {
            int k = i >> 7, n = i & 127; float v = 0.f;
            if (k < 42) {
                for (int b = 0; b < 8; b++) v += w_sbf2[n * 8 + b] * w_sbf1[b * 42 + k];
            }
            dst[k * WSTR + n] = __float2half_rn(v);
        }
    }
    {   // SBF: K=48, N=128
        __half* dst = g_wb + WE_SBF * WENT;
        for (int i = tid; i < 48 * 128; i += nt) {
            int k = i >> 7, n = i & 127;
            dst[k * WSTR + n] = __float2half_rn((k < 42) ? w_sbf[n * 42 + k] : 0.f);
        }
    }
    {   // DOWN: K=128, N=64
        __half* dst = g_wb + WE_DOWN * WENT;
        for (int i = tid; i < 128 * 64; i += nt) {
            int k = i >> 6, n = i & 63;
            dst[k * WSTR + n] = __float2half_rn(w_down[n * 128 + k]);
        }
    }
    {   // UP: K=64, N=128
        __half* dst = g_wb + WE_UP * WENT;
        for (int i = tid; i < 64 * 128; i += nt) {
            int k = i >> 7, n = i & 127;
            dst[k * WSTR + n] = __float2half_rn(w_up[n * 64 + k]);
        }
    }
    for (int c = 0; c < 3; c++) {   // TC: N=64, K 128/128/48, folded
        int kp = (c < 2) ? 128 : 48;
        __half* dst = g_wb + (WE_TC0 + c) * WENT;
        for (int i = tid; i < kp * 64; i += nt) {
            int k = i >> 6, n = i & 63, kg = c * 128 + k;
            float v = 0.f;
            if (kg < 294) {
                for (int b = 0; b < 8; b++) v += w_t2[n * 8 + b] * w_t1[b * 294 + kg];
            }
            dst[k * WSTR + n] = __float2half_rn(v);
        }
    }
}

// ---------------- staging ----------------
__device__ __forceinline__ void stageW_async(u32 smu, int entry, int K) {
    const char* src = (const char*)(g_wb + entry * WENT);
    int nbytes = K * (WSTR * 2);
    for (int i = threadIdx.x * 16; i < nbytes; i += NTHR * 16) {
        cpasync16(smu + W_OFF + i, src + i);
    }
    CP_COMMIT();
}
__device__ __forceinline__ void splitA(char* sm, int rr, int col, float a, float b) {
    __half2 h = __floats2half2_rn(a, b);
    float2 hf = __half22float2(h);
    __half2 lo = __floats2half2_rn(a - hf.x, b - hf.y);
    int off = (rr * ASTR + col) * 2;
    *(__half2*)(sm + A_HI + off) = h;
    *(__half2*)(sm + A_LO + off) = lo;
}
// 64-row tile
__device__ __forceinline__ void stage_split(char* sm, const float* __restrict__ src,
                                            int rstride, int kvalid, int npairs) {
    for (int i = threadIdx.x; i < 64 * npairs; i += NTHR) {
        int rr = i / npairs, jp = i - rr * npairs;
        float2 xv = (2 * jp < kvalid) ? *(const float2*)(src + (size_t)rr * rstride + 2 * jp)
                                      : make_float2(0.f, 0.f);
        splitA(sm, rr, 2 * jp, xv.x, xv.y);
    }
}

// ---------------- warp GEMM: 2-pass fp16 split (hi·W + lo·W); 8 warps (2M x 4N) ----------------
template<int NB>
__device__ __forceinline__ void wgemm(u32 smu, int nk, float* acc, int mrow, int ncol, int lane) {
    u32 aoff = (u32)((mrow + (lane & 15)) * ASTR + ((lane >> 4) << 3)) * 2;
    u32 boff = (u32)((lane & 15) * WSTR + ncol + ((lane >> 4) << 3)) * 2;
    u32 bBase = smu + W_OFF + boff;
    #pragma unroll
    for (int p = 0; p < 2; p++) {
        u32 aBase = smu + (p ? A_LO : A_HI) + aoff;
        for (int kc = 0; kc < nk; kc++) {
            u32 a0, a1, a2, a3, a4, a5, a6, a7;
            u32 aA = aBase + kc * 32;
            ldmA(aA, a0, a1, a2, a3);
            ldmA(aA + 16 * ASTR * 2, a4, a5, a6, a7);
            u32 bA = bBase + kc * 16 * WSTR * 2;
            #pragma unroll
            for (int nb2 = 0; nb2 < NB / 2; nb2++) {
                u32 b0, b1, b2, b3;
                ldmB4f(bA + nb2 * 32, b0, b1, b2, b3);
                mma16816(acc + nb2 * 8,                a0, a1, a2, a3, b0, b1);
                mma16816(acc + nb2 * 8 + 4,            a0, a1, a2, a3, b2, b3);
                mma16816(acc + (NB + nb2 * 2) * 4,     a4, a5, a6, a7, b0, b1);
                mma16816(acc + (NB + nb2 * 2 + 1) * 4, a4, a5, a6, a7, b2, b3);
            }
        }
    }
}

// epilogue iteration: lambda gets (rr, col, cc, idx)
template<int NB, typename F>
__device__ __forceinline__ void epi(float* acc, int mrow, int ncol, int lane, F f) {
    #pragma unroll
    for (int mt = 0; mt < 2; mt++)
    #pragma unroll
    for (int nb = 0; nb < NB; nb++) {
        int col = ncol + nb * 8 + (lane & 3) * 2;
        #pragma unroll
        for (int ri = 0; ri < 2; ri++) {
            int rr = mrow + mt * 16 + (lane >> 2) + ri * 8;
            int idx = (mt * NB + nb) * 4 + ri * 2;
            f(rr, col, acc + idx, idx);
        }
    }
}

// ---------------- Kernel A: g_t = silu((silu(x1@Wp4+b)*sbf)@Wdown), 64-row tiles ----------------
extern "C" __global__ void __launch_bounds__(NTHR, 2)
kernelA(const float* __restrict__ x1, const float* __restrict__ sbf0,
        const float* __restrict__ b_p4)
{
    extern __shared__ char sm[];
    u32 smu = smem_u32(sm);
    int tid = threadIdx.x, w = tid >> 5, lane = tid & 31;
    int mrow = (w & 1) * 32, wn = w >> 1;
    int r0 = blockIdx.x * 64;
    float acc[32], P[32];

    stageW_async(smu, WE_P4, 128);
    stage_split(sm, x1 + (size_t)r0 * 128, 128, 128, 64);
    CP_WAIT(); __syncthreads();
    za<32>(acc); wgemm<4>(smu, 8, acc, mrow, wn * 32, lane);
    __syncthreads();
    stageW_async(smu, WE_SBFC, 48);
    epi<4>(acc, mrow, wn * 32, lane, [&](int rr, int col, float* cc, int idx) {
        float2 bb = *(const float2*)(b_p4 + col);
        P[idx] = siluf(cc[0] + bb.x); P[idx + 1] = siluf(cc[1] + bb.y);
    });
    stage_split(sm, sbf0 + (size_t)r0 * 42, 42, 42, 24);
    CP_WAIT(); __syncthreads();
    za<32>(acc); wgemm<4>(smu, 3, acc, mrow, wn * 32, lane);
    __syncthreads();
    stageW_async(smu, WE_DOWN, 128);
    epi<4>(acc, mrow, wn * 32, lane, [&](int rr, int col, float* cc, int idx) {
        splitA(sm, rr, col, cc[0] * P[idx], cc[1] * P[idx + 1]);
    });
    CP_WAIT(); __syncthreads();
    za<16>(acc); wgemm<2>(smu, 8, acc, mrow, wn * 16, lane);
    epi<2>(acc, mrow, wn * 16, lane, [&](int rr, int col, float* cc, int idx) {
        *(float2*)(g_t + (size_t)(r0 + rr) * 64 + col) = make_float2(siluf(cc[0]), siluf(cc[1]));
    });
}

// ---------------- Kernel B: full tail, 64-row tiles, P in registers ----------------
extern "C" __global__ void __launch_bounds__(NTHR, 2)
kernelB(const float* __restrict__ ta, const float* __restrict__ sbf0,
        const int* __restrict__ p_idx, const float* __restrict__ x1,
        const float* __restrict__ b_p2,
        const float* __restrict__ rb_b1, const float* __restrict__ rb_b2,
        const float* __restrict__ b_lin,
        const float* __restrict__ ra_b1, const float* __restrict__ ra_b2,
        float* __restrict__ out)
{
    extern __shared__ char sm[];
    u32 smu = smem_u32(sm);
    int tid = threadIdx.x, w = tid >> 5, lane = tid & 31;
    int mrow = (w & 1) * 32, wn = w >> 1;
    int r0 = blockIdx.x * 64;
    float acc[32], P[32];
    int nc128 = wn * 32, nc64 = wn * 16;

    // G1: x_p2 = silu(x1@Wp2 + b) -> P regs
    stageW_async(smu, WE_P2, 128);
    stage_split(sm, x1 + (size_t)r0 * 128, 128, 128, 64);
    CP_WAIT(); __syncthreads();
    za<32>(acc); wgemm<4>(smu, 8, acc, mrow, nc128, lane);
    __syncthreads();
    stageW_async(smu, WE_TC0, 128);
    epi<4>(acc, mrow, nc128, lane, [&](int rr, int col, float* cc, int idx) {
        float2 bb = *(const float2*)(b_p2 + col);
        P[idx] = siluf(cc[0] + bb.x); P[idx + 1] = siluf(cc[1] + bb.y);
    });
    stage_split(sm, ta + (size_t)r0 * 294 + 0, 294, 128, 64);
    CP_WAIT(); __syncthreads();

    // G2: ta_p = ta@WtC (3 chunks, reg-accumulated)
    za<16>(acc);
    wgemm<2>(smu, 8, acc, mrow, nc64, lane);
    __syncthreads();
    stageW_async(smu, WE_TC1, 128);
    stage_split(sm, ta + (size_t)r0 * 294 + 128, 294, 128, 64);
    CP_WAIT(); __syncthreads();
    wgemm<2>(smu, 8, acc, mrow, nc64, lane);
    __syncthreads();
    stageW_async(smu, WE_TC2, 48);
    stage_split(sm, ta + (size_t)r0 * 294 + 256, 294, 38, 24);
    CP_WAIT(); __syncthreads();
    wgemm<2>(smu, 3, acc, mrow, nc64, lane);
    __syncthreads();
    stageW_async(smu, WE_UP, 64);
    epi<2>(acc, mrow, nc64, lane, [&](int rr, int col, float* cc, int idx) {
        int idxg = p_idx[r0 + rr];
        float2 tv = *(const float2*)(g_t + (size_t)idxg * 64 + col);
        splitA(sm, rr, col, cc[0] * tv.x, cc[1] * tv.y);
    });
    CP_WAIT(); __syncthreads();

    // G3: p1 = silu(g@Wup) + x_p2 -> P regs, A
    za<32>(acc); wgemm<4>(smu, 4, acc, mrow, nc128, lane);
    __syncthreads();
    stageW_async(smu, WE_RB1, 128);
    epi<4>(acc, mrow, nc128, lane, [&](int rr, int col, float* cc, int idx) {
        float v0 = siluf(cc[0]) + P[idx];
        float v1 = siluf(cc[1]) + P[idx + 1];
        P[idx] = v0; P[idx + 1] = v1;
        splitA(sm, rr, col, v0, v1);
    });
    CP_WAIT(); __syncthreads();

    // G4..G9: RB1, RB2, LIN, RA1A, RA2A, RA1B (prefetch next; bias matches current)
    const int entN[6] = { WE_RB2, WE_LIN, WE_RA1A, WE_RA2A, WE_RA1B, WE_RA2B };
    const float* bs1[6] = { rb_b1, rb_b2, b_lin, ra_b1, ra_b2, ra_b1 + 128 };
    #pragma unroll 1
    for (int s = 0; s < 6; s++) {
        za<32>(acc); wgemm<4>(smu, 8, acc, mrow, nc128, lane);
        __syncthreads();
        stageW_async(smu, entN[s], 128);
        const float* bb_ = bs1[s];
        if (s == 0 || s == 3 || s == 5) {           // first half of res block: A = silu(v+b)
            epi<4>(acc, mrow, nc128, lane, [&](int rr, int col, float* cc, int idx) {
                float2 bb = *(const float2*)(bb_ + col);
                splitA(sm, rr, col, siluf(cc[0] + bb.x), siluf(cc[1] + bb.y));
            });
        } else if (s == 1 || s == 4) {              // second half: P += silu(v+b); A = P
            epi<4>(acc, mrow, nc128, lane, [&](int rr, int col, float* cc, int idx) {
                float2 bb = *(const float2*)(bb_ + col);
                float v0 = P[idx] + siluf(cc[0] + bb.x);
                float v1 = P[idx + 1] + siluf(cc[1] + bb.y);
                P[idx] = v0; P[idx + 1] = v1;
                splitA(sm, rr, col, v0, v1);
            });
        } else {                                    // lin: P = silu(v+b) + x1; A = P
            epi<4>(acc, mrow, nc128, lane, [&](int rr, int col, float* cc, int idx) {
                float2 bb = *(const float2*)(bb_ + col);
                float2 xv = *(const float2*)(x1 + (size_t)(r0 + rr) * 128 + col);
                float v0 = siluf(cc[0] + bb.x) + xv.x;
                float v1 = siluf(cc[1] + bb.y) + xv.y;
                P[idx] = v0; P[idx + 1] = v1;
                splitA(sm, rr, col, v0, v1);
            });
        }
        CP_WAIT(); __syncthreads();
    }

    // G10: RA2B — p1 final: P += silu(v+b); write out p1
    za<32>(acc); wgemm<4>(smu, 8, acc, mrow, nc128, lane);
    __syncthreads();
    stageW_async(smu, WE_SBF, 48);
    epi<4>(acc, mrow, nc128, lane, [&](int rr, int col, float* cc, int idx) {
        float2 bb = *(const float2*)(ra_b2 + 128 + col);
        float v0 = P[idx] + siluf(cc[0] + bb.x);
        float v1 = P[idx + 1] + siluf(cc[1] + bb.y);
        P[idx] = v0; P[idx + 1] = v1;
        *(float2*)(out + (size_t)(r0 + rr) * 128 + col) = make_float2(v0, v1);
    });
    stage_split(sm, sbf0 + (size_t)r0 * 42, 42, 42, 24);
    CP_WAIT(); __syncthreads();

    // G11: p2 = (sbf0@Wsbf) * p1
    za<32>(acc); wgemm<4>(smu, 3, acc, mrow, nc128, lane);
    float* out2 = out + (size_t)E_EDGES * 128;
    epi<4>(acc, mrow, nc128, lane, [&](int rr, int col, float* cc, int idx) {
        *(float2*)(out2 + (size_t)(r0 + rr) * 128 + col) = make_float2(cc[0] * P[idx], cc[1] * P[idx + 1]);
    });
}

// ---------------- launch ----------------
extern "C" void kernel_launch(void* const* d_in, const int* in_sizes, int n_in,
                              void* d_out, int out_size)
{
    const float* x1     = (const float*)d_in[0];
    const float* sbf0   = (const float*)d_in[1];
    const float* ta     = (const float*)d_in[2];
    const int*   p_idx  = (const int*)  d_in[3];
    const float* w_p2   = (const float*)d_in[4];
    const float* b_p2   = (const float*)d_in[5];
    const float* w_p4   = (const float*)d_in[6];
    const float* b_p4   = (const float*)d_in[7];
    const float* w_sbf1 = (const float*)d_in[8];
    const float* w_sbf2 = (const float*)d_in[9];
    const float* w_t1   = (const float*)d_in[10];
    const float* w_t2   = (const float*)d_in[11];
    const float* w_down = (const float*)d_in[12];
    const float* w_up   = (const float*)d_in[13];
    const float* rb_w1  = (const float*)d_in[14];
    const float* rb_b1  = (const float*)d_in[15];
    const float* rb_w2  = (const float*)d_in[16];
    const float* rb_b2  = (const float*)d_in[17];
    const float* w_lin  = (const float*)d_in[18];
    const float* b_lin  = (const float*)d_in[19];
    const float* ra_w1  = (const float*)d_in[20];
    const float* ra_b1  = (const float*)d_in[21];
    const float* ra_w2  = (const float*)d_in[22];
    const float* ra_b2  = (const float*)d_in[23];
    const float* w_sbf  = (const float*)d_in[24];
    float* out = (float*)d_out;

    cudaFuncSetAttribute(kernelA, cudaFuncAttributeMaxDynamicSharedMemorySize, SMEM_TOTAL);
    cudaFuncSetAttribute(kernelB, cudaFuncAttributeMaxDynamicSharedMemorySize, SMEM_TOTAL);

    setup_kernel<<<128, 256>>>(w_p2, w_p4, w_sbf1, w_sbf2, w_t1, w_t2, w_down, w_up,
                               rb_w1, rb_w2, w_lin, ra_w1, ra_w2, w_sbf);
    kernelA<<<E_EDGES / 64, NTHR, SMEM_TOTAL>>>(x1, sbf0, b_p4);
    kernelB<<<E_EDGES / 64, NTHR, SMEM_TOTAL>>>(ta, sbf0, p_idx, x1, b_p2,
                                                rb_b1, rb_b2, b_lin, ra_b1, ra_b2, out);
}